// round 1
// baseline (speedup 1.0000x reference)
#include <cuda_runtime.h>
#include <cuda_bf16.h>
#include <cstdint>

// ---------------------------------------------------------------------------
// Problem constants
// ---------------------------------------------------------------------------
#define T_STEPS 1000
#define BATCH   64
#define NIN     256
#define NHID    512
#define NOUT    128
#define M_ROWS  (T_STEPS * BATCH)   // 64000

// GLIF constants
#define V_TH     (-45.0f)
#define V_RESET  (-60.0f)
#define DT_CM    (0.5f)     // DT / C_M
#define DECAY_V  (0.05f)    // DT / TAU
#define D_ASC0   (0.9048374180359595f)   // exp(-0.1)
#define D_ASC1   (0.8187307530779818f)   // exp(-0.2)
#define D_SYN    (0.8187307530779818f)   // exp(-0.2)
#define AMP0     (1.0f)
#define AMP1     (-2.0f)

// ---------------------------------------------------------------------------
// Device scratch (static — no allocation allowed)
// ---------------------------------------------------------------------------
__device__ __align__(128) __nv_bfloat16 g_xb[(size_t)M_ROWS * NIN];   // 32.8 MB
__device__ __align__(128) __nv_bfloat16 g_wb[NHID * NIN];             // 256 KB
__device__ __align__(128) float g_xproj[(size_t)M_ROWS * NHID];       // 131 MB
__device__ __align__(128) float g_wrecT[NHID * NHID];                 // 1 MB
__device__ __align__(128) float g_rate[BATCH * NHID];                 // 128 KB

// ---------------------------------------------------------------------------
// Convert x (fp32) -> bf16
// ---------------------------------------------------------------------------
__global__ void cvt_x_kernel(const float4* __restrict__ in) {
    int i = blockIdx.x * blockDim.x + threadIdx.x;   // i < 4,096,000
    float4 v = in[i];
    __nv_bfloat162 lo = __floats2bfloat162_rn(v.x, v.y);
    __nv_bfloat162 hi = __floats2bfloat162_rn(v.z, v.w);
    reinterpret_cast<__nv_bfloat162*>(g_xb)[2 * i]     = lo;
    reinterpret_cast<__nv_bfloat162*>(g_xb)[2 * i + 1] = hi;
}

__global__ void cvt_w_kernel(const float4* __restrict__ in) {
    int i = blockIdx.x * blockDim.x + threadIdx.x;   // i < 32768
    float4 v = in[i];
    __nv_bfloat162 lo = __floats2bfloat162_rn(v.x, v.y);
    __nv_bfloat162 hi = __floats2bfloat162_rn(v.z, v.w);
    reinterpret_cast<__nv_bfloat162*>(g_wb)[2 * i]     = lo;
    reinterpret_cast<__nv_bfloat162*>(g_wb)[2 * i + 1] = hi;
}

// ---------------------------------------------------------------------------
// Transpose W_rec (512x512) so recurrent gather reads are coalesced over h:
//   g_wrecT[j][h] = W_rec[h][j]
// ---------------------------------------------------------------------------
__global__ void transpose_wrec_kernel(const float* __restrict__ w) {
    int j = blockIdx.x;
    int h = threadIdx.x;
    g_wrecT[j * NHID + h] = w[h * NHID + j];
}

// ---------------------------------------------------------------------------
// GEMM: x_proj[m][n] = sum_k xb[m][k] * wb[n][k]   (bf16 inputs, fp32 accum)
// Tiles: BM=128, BN=128, full K=256 resident in SMEM (no k-pipeline needed).
// 256 threads = 8 warps, each warp computes a 64x32 sub-tile via m16n8k16 mma.
// ---------------------------------------------------------------------------
#define BM 128
#define BN 128
#define GPITCH 264    // 256 + 8 bf16 padding -> conflict-free 32-bit LDS

__global__ void __launch_bounds__(256) gemm_bf16_kernel() {
    extern __shared__ __nv_bfloat16 smem[];
    __nv_bfloat16* sA = smem;                  // BM * GPITCH
    __nv_bfloat16* sB = smem + BM * GPITCH;    // BN * GPITCH

    const int tid = threadIdx.x;
    const long tileM = (long)blockIdx.x * BM;
    const int  tileN = blockIdx.y * BN;

    // Load A tile (128 x 256) and B tile (128 x 256) as 16B chunks
#pragma unroll
    for (int i = 0; i < 16; ++i) {
        int idx = tid + i * 256;             // 0 .. 4095
        int r = idx >> 5;                    // row 0..127
        int c = (idx & 31) << 3;             // col 0..248 step 8
        *reinterpret_cast<uint4*>(sA + r * GPITCH + c) =
            *reinterpret_cast<const uint4*>(g_xb + (tileM + r) * NIN + c);
        *reinterpret_cast<uint4*>(sB + r * GPITCH + c) =
            *reinterpret_cast<const uint4*>(g_wb + (long)(tileN + r) * NIN + c);
    }
    __syncthreads();

    const int warp = tid >> 5, lane = tid & 31;
    const int wm = warp & 1;        // 0..1  (64-row slabs)
    const int wn = warp >> 1;       // 0..3  (32-col slabs)
    const int g  = lane >> 2;       // group id 0..7
    const int tg = lane & 3;        // thread-in-group 0..3

    const __nv_bfloat16* wA = sA + (wm * 64 + g) * GPITCH + tg * 2;
    const __nv_bfloat16* wB = sB + (wn * 32 + g) * GPITCH + tg * 2;

    float acc[4][4][4];
#pragma unroll
    for (int a = 0; a < 4; ++a)
#pragma unroll
        for (int b = 0; b < 4; ++b)
#pragma unroll
            for (int c = 0; c < 4; ++c) acc[a][b][c] = 0.f;

#pragma unroll
    for (int ks = 0; ks < 16; ++ks) {
        const int k0 = ks * 16;
        uint32_t af[4][4], bfr[4][2];
#pragma unroll
        for (int mt = 0; mt < 4; ++mt) {
            const __nv_bfloat16* p = wA + mt * 16 * GPITCH + k0;
            af[mt][0] = *reinterpret_cast<const uint32_t*>(p);
            af[mt][1] = *reinterpret_cast<const uint32_t*>(p + 8 * GPITCH);
            af[mt][2] = *reinterpret_cast<const uint32_t*>(p + 8);
            af[mt][3] = *reinterpret_cast<const uint32_t*>(p + 8 * GPITCH + 8);
        }
#pragma unroll
        for (int nt = 0; nt < 4; ++nt) {
            const __nv_bfloat16* p = wB + nt * 8 * GPITCH + k0;
            bfr[nt][0] = *reinterpret_cast<const uint32_t*>(p);
            bfr[nt][1] = *reinterpret_cast<const uint32_t*>(p + 8);
        }
#pragma unroll
        for (int mt = 0; mt < 4; ++mt)
#pragma unroll
            for (int nt = 0; nt < 4; ++nt)
                asm volatile(
                    "mma.sync.aligned.m16n8k16.row.col.f32.bf16.bf16.f32 "
                    "{%0,%1,%2,%3}, {%4,%5,%6,%7}, {%8,%9}, {%0,%1,%2,%3};\n"
                    : "+f"(acc[mt][nt][0]), "+f"(acc[mt][nt][1]),
                      "+f"(acc[mt][nt][2]), "+f"(acc[mt][nt][3])
                    : "r"(af[mt][0]), "r"(af[mt][1]), "r"(af[mt][2]), "r"(af[mt][3]),
                      "r"(bfr[nt][0]), "r"(bfr[nt][1]));
    }

    // Epilogue: fp32 store to g_xproj
#pragma unroll
    for (int mt = 0; mt < 4; ++mt) {
        long row0 = tileM + wm * 64 + mt * 16 + g;
#pragma unroll
        for (int nt = 0; nt < 4; ++nt) {
            int col = tileN + wn * 32 + nt * 8 + tg * 2;
            *reinterpret_cast<float2*>(g_xproj + row0 * NHID + col) =
                make_float2(acc[mt][nt][0], acc[mt][nt][1]);
            *reinterpret_cast<float2*>(g_xproj + (row0 + 8) * NHID + col) =
                make_float2(acc[mt][nt][2], acc[mt][nt][3]);
        }
    }
}

// ---------------------------------------------------------------------------
// Scan kernel: 64 CTAs (one per batch), 512 threads (one per hidden neuron).
// State in registers. Recurrent term via ballot compaction; W_recT gathered
// coalesced from L2. Double-buffered ballots -> one __syncthreads per step.
// Depth-8 register prefetch of the I_in stream hides DRAM latency.
// ---------------------------------------------------------------------------
#define PF_DEPTH 8

__global__ void __launch_bounds__(512) scan_kernel() {
    const int b = blockIdx.x;
    const int h = threadIdx.x;
    const int warp = h >> 5, lane = h & 31;

    __shared__ unsigned s_bal[2][16];

    float v   = V_RESET;
    float a0  = 0.f, a1 = 0.f;
    float psc = 0.f;
    float cnt = 0.f;

    const long stride = (long)BATCH * NHID;
    const float* __restrict__ xp = g_xproj + (long)b * NHID + h;

    float buf[PF_DEPTH];
#pragma unroll
    for (int d = 0; d < PF_DEPTH; ++d) buf[d] = xp[(long)d * stride];

    for (int t = 0; t < T_STEPS; t += PF_DEPTH) {
#pragma unroll
        for (int d = 0; d < PF_DEPTH; ++d) {
            float I = buf[d];
            int tn = t + d + PF_DEPTH;
            if (tn > T_STEPS - 1) tn = T_STEPS - 1;    // tail value never consumed
            buf[d] = xp[(long)tn * stride];

            float Itot  = I + psc + a0 + a1;
            float v_int = v + DT_CM * Itot - DECAY_V * (v - V_RESET);
            bool  sp    = v_int >= V_TH;

            unsigned bal = __ballot_sync(0xffffffffu, sp);
            int pb = (t + d) & 1;
            if (lane == 0) s_bal[pb][warp] = bal;
            __syncthreads();

            v  = sp ? V_RESET : v_int;
            a0 = a0 * D_ASC0 + (sp ? AMP0 : 0.f);
            a1 = a1 * D_ASC1 + (sp ? AMP1 : 0.f);
            cnt += sp ? 1.f : 0.f;

            float rec = 0.f;
#pragma unroll
            for (int w = 0; w < 16; ++w) {
                unsigned word = s_bal[pb][w];
                while (word) {
                    int j = (w << 5) + __ffs(word) - 1;
                    word &= word - 1;
                    rec += g_wrecT[j * NHID + h];
                }
            }
            psc = psc * D_SYN + rec;
        }
    }

    g_rate[b * NHID + h] = cnt * (1.0f / T_STEPS);
}

// ---------------------------------------------------------------------------
// Output: out[b][o] = sum_h rate[b][h] * W_out[o][h]
// ---------------------------------------------------------------------------
__global__ void __launch_bounds__(128) out_kernel(const float* __restrict__ W_out,
                                                  float* __restrict__ out) {
    const int b = blockIdx.x;
    const int o = threadIdx.x;
    __shared__ float sr[NHID];
    for (int i = o; i < NHID; i += 128) sr[i] = g_rate[b * NHID + i];
    __syncthreads();

    float acc = 0.f;
    const float4* w = reinterpret_cast<const float4*>(W_out + o * NHID);
#pragma unroll 4
    for (int i = 0; i < NHID / 4; ++i) {
        float4 wv = w[i];
        acc += wv.x * sr[4 * i] + wv.y * sr[4 * i + 1]
             + wv.z * sr[4 * i + 2] + wv.w * sr[4 * i + 3];
    }
    out[b * NOUT + o] = acc;
}

// ---------------------------------------------------------------------------
// Launch
// ---------------------------------------------------------------------------
extern "C" void kernel_launch(void* const* d_in, const int* in_sizes, int n_in,
                              void* d_out, int out_size) {
    const float* x     = (const float*)d_in[0];   // (1000, 64, 256)
    // d_in[1] = W_in (512, 256)
    const float* W_rec = (const float*)d_in[2];   // (512, 512)
    const float* W_out = (const float*)d_in[3];   // (128, 512)
    float* out = (float*)d_out;                   // (64, 128)

    (void)in_sizes; (void)n_in; (void)out_size;

    // bf16 conversions
    cvt_x_kernel<<<16000, 256>>>(reinterpret_cast<const float4*>(x));
    cvt_w_kernel<<<128, 256>>>(reinterpret_cast<const float4*>(d_in[1]));

    // W_rec transpose
    transpose_wrec_kernel<<<NHID, NHID>>>(W_rec);

    // Input projection GEMM
    const int smem_bytes = 2 * BM * GPITCH * (int)sizeof(__nv_bfloat16);  // 135168
    cudaFuncSetAttribute(gemm_bf16_kernel,
                         cudaFuncAttributeMaxDynamicSharedMemorySize, smem_bytes);
    gemm_bf16_kernel<<<dim3(M_ROWS / BM, NHID / BN), 256, smem_bytes>>>();

    // Sequential scan (per-batch CTAs, fully independent)
    scan_kernel<<<BATCH, NHID>>>();

    // Output projection
    out_kernel<<<BATCH, NOUT>>>(W_out, out);
}

// round 2
// speedup vs baseline: 2.5071x; 2.5071x over previous
#include <cuda_runtime.h>
#include <cuda_bf16.h>
#include <cstdint>

// ---------------------------------------------------------------------------
// Problem constants
// ---------------------------------------------------------------------------
#define T_STEPS 1000
#define BATCH   64
#define NIN     256
#define NHID    512
#define NOUT    128
#define M_ROWS  (T_STEPS * BATCH)   // 64000

// GLIF constants
#define V_TH     (-45.0f)
#define V_RESET  (-60.0f)
#define DT_CM    (0.5f)     // DT / C_M
#define DECAY_V  (0.05f)    // DT / TAU
#define D_ASC0   (0.9048374180359595f)   // exp(-0.1)
#define D_ASC1   (0.8187307530779818f)   // exp(-0.2)
#define D_SYN    (0.8187307530779818f)   // exp(-0.2)
#define AMP0     (1.0f)
#define AMP1     (-2.0f)

// ---------------------------------------------------------------------------
// Device scratch (static — no allocation allowed)
// ---------------------------------------------------------------------------
__device__ __align__(128) __nv_bfloat16 g_xb[(size_t)M_ROWS * NIN];   // 32.8 MB
__device__ __align__(128) __nv_bfloat16 g_wb[NHID * NIN];             // 256 KB
__device__ __align__(128) float g_xproj[(size_t)M_ROWS * NHID];       // 131 MB
__device__ __align__(128) float g_wrecT[NHID * NHID];                 // 1 MB
__device__ __align__(128) float g_rate[BATCH * NHID];                 // 128 KB

// ---------------------------------------------------------------------------
// Convert x (fp32) -> bf16
// ---------------------------------------------------------------------------
__global__ void cvt_x_kernel(const float4* __restrict__ in) {
    int i = blockIdx.x * blockDim.x + threadIdx.x;   // i < 4,096,000
    float4 v = in[i];
    __nv_bfloat162 lo = __floats2bfloat162_rn(v.x, v.y);
    __nv_bfloat162 hi = __floats2bfloat162_rn(v.z, v.w);
    reinterpret_cast<__nv_bfloat162*>(g_xb)[2 * i]     = lo;
    reinterpret_cast<__nv_bfloat162*>(g_xb)[2 * i + 1] = hi;
}

__global__ void cvt_w_kernel(const float4* __restrict__ in) {
    int i = blockIdx.x * blockDim.x + threadIdx.x;   // i < 32768
    float4 v = in[i];
    __nv_bfloat162 lo = __floats2bfloat162_rn(v.x, v.y);
    __nv_bfloat162 hi = __floats2bfloat162_rn(v.z, v.w);
    reinterpret_cast<__nv_bfloat162*>(g_wb)[2 * i]     = lo;
    reinterpret_cast<__nv_bfloat162*>(g_wb)[2 * i + 1] = hi;
}

// ---------------------------------------------------------------------------
// Transpose W_rec (512x512): g_wrecT[j][h] = W_rec[h][j]
// ---------------------------------------------------------------------------
__global__ void transpose_wrec_kernel(const float* __restrict__ w) {
    int j = blockIdx.x;
    int h = threadIdx.x;
    g_wrecT[j * NHID + h] = w[h * NHID + j];
}

// ---------------------------------------------------------------------------
// GEMM: x_proj[m][n] = sum_k xb[m][k] * wb[n][k]   (bf16 inputs, fp32 accum)
// ---------------------------------------------------------------------------
#define BM 128
#define BN 128
#define GPITCH 264    // 256 + 8 bf16 padding -> conflict-free 32-bit LDS

__global__ void __launch_bounds__(256) gemm_bf16_kernel() {
    extern __shared__ __nv_bfloat16 smem[];
    __nv_bfloat16* sA = smem;                  // BM * GPITCH
    __nv_bfloat16* sB = smem + BM * GPITCH;    // BN * GPITCH

    const int tid = threadIdx.x;
    const long tileM = (long)blockIdx.x * BM;
    const int  tileN = blockIdx.y * BN;

#pragma unroll
    for (int i = 0; i < 16; ++i) {
        int idx = tid + i * 256;             // 0 .. 4095
        int r = idx >> 5;                    // row 0..127
        int c = (idx & 31) << 3;             // col 0..248 step 8
        *reinterpret_cast<uint4*>(sA + r * GPITCH + c) =
            *reinterpret_cast<const uint4*>(g_xb + (tileM + r) * NIN + c);
        *reinterpret_cast<uint4*>(sB + r * GPITCH + c) =
            *reinterpret_cast<const uint4*>(g_wb + (long)(tileN + r) * NIN + c);
    }
    __syncthreads();

    const int warp = tid >> 5, lane = tid & 31;
    const int wm = warp & 1;        // 0..1  (64-row slabs)
    const int wn = warp >> 1;       // 0..3  (32-col slabs)
    const int g  = lane >> 2;       // group id 0..7
    const int tg = lane & 3;        // thread-in-group 0..3

    const __nv_bfloat16* wA = sA + (wm * 64 + g) * GPITCH + tg * 2;
    const __nv_bfloat16* wB = sB + (wn * 32 + g) * GPITCH + tg * 2;

    float acc[4][4][4];
#pragma unroll
    for (int a = 0; a < 4; ++a)
#pragma unroll
        for (int b = 0; b < 4; ++b)
#pragma unroll
            for (int c = 0; c < 4; ++c) acc[a][b][c] = 0.f;

#pragma unroll
    for (int ks = 0; ks < 16; ++ks) {
        const int k0 = ks * 16;
        uint32_t af[4][4], bfr[4][2];
#pragma unroll
        for (int mt = 0; mt < 4; ++mt) {
            const __nv_bfloat16* p = wA + mt * 16 * GPITCH + k0;
            af[mt][0] = *reinterpret_cast<const uint32_t*>(p);
            af[mt][1] = *reinterpret_cast<const uint32_t*>(p + 8 * GPITCH);
            af[mt][2] = *reinterpret_cast<const uint32_t*>(p + 8);
            af[mt][3] = *reinterpret_cast<const uint32_t*>(p + 8 * GPITCH + 8);
        }
#pragma unroll
        for (int nt = 0; nt < 4; ++nt) {
            const __nv_bfloat16* p = wB + nt * 8 * GPITCH + k0;
            bfr[nt][0] = *reinterpret_cast<const uint32_t*>(p);
            bfr[nt][1] = *reinterpret_cast<const uint32_t*>(p + 8);
        }
#pragma unroll
        for (int mt = 0; mt < 4; ++mt)
#pragma unroll
            for (int nt = 0; nt < 4; ++nt)
                asm volatile(
                    "mma.sync.aligned.m16n8k16.row.col.f32.bf16.bf16.f32 "
                    "{%0,%1,%2,%3}, {%4,%5,%6,%7}, {%8,%9}, {%0,%1,%2,%3};\n"
                    : "+f"(acc[mt][nt][0]), "+f"(acc[mt][nt][1]),
                      "+f"(acc[mt][nt][2]), "+f"(acc[mt][nt][3])
                    : "r"(af[mt][0]), "r"(af[mt][1]), "r"(af[mt][2]), "r"(af[mt][3]),
                      "r"(bfr[nt][0]), "r"(bfr[nt][1]));
    }

#pragma unroll
    for (int mt = 0; mt < 4; ++mt) {
        long row0 = tileM + wm * 64 + mt * 16 + g;
#pragma unroll
        for (int nt = 0; nt < 4; ++nt) {
            int col = tileN + wn * 32 + nt * 8 + tg * 2;
            *reinterpret_cast<float2*>(g_xproj + row0 * NHID + col) =
                make_float2(acc[mt][nt][0], acc[mt][nt][1]);
            *reinterpret_cast<float2*>(g_xproj + (row0 + 8) * NHID + col) =
                make_float2(acc[mt][nt][2], acc[mt][nt][3]);
        }
    }
}

// ---------------------------------------------------------------------------
// Scan kernel v2: 64 CTAs (one per batch), 128 threads, 4 neurons/thread.
// Fast path (no spike anywhere, the overwhelmingly common case): one
// __syncthreads_or per step, psc just decays. Slow path (any spike): build a
// 512-bit spike mask in smem via atomicOr, gather W_recT columns (float4,
// coalesced). Depth-8 float4 register prefetch hides x_proj DRAM latency.
// ---------------------------------------------------------------------------
#define PF_DEPTH 8

__global__ void __launch_bounds__(128) scan_kernel() {
    const int b = blockIdx.x;
    const int tid = threadIdx.x;          // covers neurons 4*tid .. 4*tid+3

    __shared__ unsigned s_mask[16];

    float v[4], a0[4], a1[4], psc[4], cnt[4];
#pragma unroll
    for (int i = 0; i < 4; ++i) {
        v[i] = V_RESET; a0[i] = 0.f; a1[i] = 0.f; psc[i] = 0.f; cnt[i] = 0.f;
    }

    const long stride4 = (long)BATCH * NHID / 4;   // float4 units per timestep
    const float4* __restrict__ xp =
        reinterpret_cast<const float4*>(g_xproj) + (long)b * (NHID / 4) + tid;

    float4 buf[PF_DEPTH];
#pragma unroll
    for (int d = 0; d < PF_DEPTH; ++d) buf[d] = xp[(long)d * stride4];

    for (int t = 0; t < T_STEPS; t += PF_DEPTH) {
#pragma unroll
        for (int d = 0; d < PF_DEPTH; ++d) {
            float4 I4 = buf[d];
            int tn = t + d + PF_DEPTH;
            if (tn > T_STEPS - 1) tn = T_STEPS - 1;   // tail value never consumed
            buf[d] = xp[(long)tn * stride4];

            float Ii[4] = {I4.x, I4.y, I4.z, I4.w};
            bool sp[4];
#pragma unroll
            for (int i = 0; i < 4; ++i) {
                float Itot  = Ii[i] + psc[i] + a0[i] + a1[i];
                float v_int = v[i] + DT_CM * Itot - DECAY_V * (v[i] - V_RESET);
                sp[i] = v_int >= V_TH;
                v[i]  = sp[i] ? V_RESET : v_int;
                a0[i] = a0[i] * D_ASC0 + (sp[i] ? AMP0 : 0.f);
                a1[i] = a1[i] * D_ASC1 + (sp[i] ? AMP1 : 0.f);
                cnt[i] += sp[i] ? 1.f : 0.f;
            }
            int anyl = (int)(sp[0] | sp[1] | sp[2] | sp[3]);

            if (__syncthreads_or(anyl)) {
                // ---- rare slow path: full recurrent gather ----
                if (tid < 16) s_mask[tid] = 0;
                __syncthreads();
                unsigned nib = (unsigned)sp[0] | ((unsigned)sp[1] << 1)
                             | ((unsigned)sp[2] << 2) | ((unsigned)sp[3] << 3);
                if (nib) atomicOr(&s_mask[tid >> 3], nib << (4 * (tid & 7)));
                __syncthreads();
                float rec[4] = {0.f, 0.f, 0.f, 0.f};
#pragma unroll 1
                for (int w = 0; w < 16; ++w) {
                    unsigned word = s_mask[w];
                    while (word) {
                        int j = (w << 5) + __ffs(word) - 1;
                        word &= word - 1;
                        float4 wv = *reinterpret_cast<const float4*>(
                            g_wrecT + j * NHID + 4 * tid);
                        rec[0] += wv.x; rec[1] += wv.y;
                        rec[2] += wv.z; rec[3] += wv.w;
                    }
                }
                __syncthreads();   // protect s_mask reuse
#pragma unroll
                for (int i = 0; i < 4; ++i) psc[i] = psc[i] * D_SYN + rec[i];
            } else {
                // ---- fast path: no spikes anywhere this step ----
#pragma unroll
                for (int i = 0; i < 4; ++i) psc[i] *= D_SYN;
            }
        }
    }

    float4 r = make_float4(cnt[0] * (1.0f / T_STEPS), cnt[1] * (1.0f / T_STEPS),
                           cnt[2] * (1.0f / T_STEPS), cnt[3] * (1.0f / T_STEPS));
    reinterpret_cast<float4*>(g_rate)[b * (NHID / 4) + tid] = r;
}

// ---------------------------------------------------------------------------
// Output: out[b][o] = sum_h rate[b][h] * W_out[o][h]
// ---------------------------------------------------------------------------
__global__ void __launch_bounds__(128) out_kernel(const float* __restrict__ W_out,
                                                  float* __restrict__ out) {
    const int b = blockIdx.x;
    const int o = threadIdx.x;
    __shared__ float sr[NHID];
    for (int i = o; i < NHID; i += 128) sr[i] = g_rate[b * NHID + i];
    __syncthreads();

    float acc = 0.f;
    const float4* w = reinterpret_cast<const float4*>(W_out + o * NHID);
#pragma unroll 4
    for (int i = 0; i < NHID / 4; ++i) {
        float4 wv = w[i];
        acc += wv.x * sr[4 * i] + wv.y * sr[4 * i + 1]
             + wv.z * sr[4 * i + 2] + wv.w * sr[4 * i + 3];
    }
    out[b * NOUT + o] = acc;
}

// ---------------------------------------------------------------------------
// Launch
// ---------------------------------------------------------------------------
extern "C" void kernel_launch(void* const* d_in, const int* in_sizes, int n_in,
                              void* d_out, int out_size) {
    const float* x     = (const float*)d_in[0];   // (1000, 64, 256)
    // d_in[1] = W_in (512, 256)
    const float* W_rec = (const float*)d_in[2];   // (512, 512)
    const float* W_out = (const float*)d_in[3];   // (128, 512)
    float* out = (float*)d_out;                   // (64, 128)

    (void)in_sizes; (void)n_in; (void)out_size;

    cvt_x_kernel<<<16000, 256>>>(reinterpret_cast<const float4*>(x));
    cvt_w_kernel<<<128, 256>>>(reinterpret_cast<const float4*>(d_in[1]));

    transpose_wrec_kernel<<<NHID, NHID>>>(W_rec);

    const int smem_bytes = 2 * BM * GPITCH * (int)sizeof(__nv_bfloat16);  // 135168
    cudaFuncSetAttribute(gemm_bf16_kernel,
                         cudaFuncAttributeMaxDynamicSharedMemorySize, smem_bytes);
    gemm_bf16_kernel<<<dim3(M_ROWS / BM, NHID / BN), 256, smem_bytes>>>();

    scan_kernel<<<BATCH, 128>>>();

    out_kernel<<<BATCH, NOUT>>>(W_out, out);
}

// round 3
// speedup vs baseline: 4.2979x; 1.7143x over previous
#include <cuda_runtime.h>
#include <cuda_bf16.h>
#include <cstdint>

// ---------------------------------------------------------------------------
// Problem constants
// ---------------------------------------------------------------------------
#define T_STEPS 1000
#define BATCH   64
#define NIN     256
#define NHID    512
#define NOUT    128
#define M_ROWS  (T_STEPS * BATCH)   // 64000

// GLIF constants
#define V_TH     (-45.0f)
#define V_RESET  (-60.0f)
#define DT_CM    (0.5f)     // DT / C_M
#define DECAY_V  (0.05f)    // DT / TAU
#define D_ASC0   (0.9048374180359595f)   // exp(-0.1)
#define D_ASC1   (0.8187307530779818f)   // exp(-0.2)
#define D_SYN    (0.8187307530779818f)   // exp(-0.2)
#define AMP0     (1.0f)
#define AMP1     (-2.0f)

// ---------------------------------------------------------------------------
// Device scratch (static — no allocation allowed)
// ---------------------------------------------------------------------------
__device__ __align__(128) __nv_bfloat16 g_xproj[(size_t)M_ROWS * NHID]; // 65.5 MB
__device__ __align__(128) float g_wrecT[NHID * NHID];                   // 1 MB
__device__ __align__(128) float g_rate[BATCH * NHID];                   // 128 KB
__device__ int g_flag;

// ---------------------------------------------------------------------------
// Reset the spike flag (graph replays must be deterministic)
// ---------------------------------------------------------------------------
__global__ void reset_flag_kernel() { g_flag = 0; }

// ---------------------------------------------------------------------------
// Transpose W_rec (512x512): g_wrecT[j][h] = W_rec[h][j]  (used only by the
// rare fallback path)
// ---------------------------------------------------------------------------
__global__ void transpose_wrec_kernel(const float* __restrict__ w) {
    int j = blockIdx.x;
    int h = threadIdx.x;
    g_wrecT[j * NHID + h] = w[h * NHID + j];
}

// ---------------------------------------------------------------------------
// GEMM: x_proj[m][n] = sum_k x[m][k] * W_in[n][k]
// fp32 inputs converted inline to bf16 in smem; fp32 accum; bf16 output.
// BM=256, BN=128, full K=256 resident. 512 threads = 16 warps, warp grid
// 4(m)x4(n), each warp a 64x32 sub-tile via m16n8k16 mma.
// Grid is N-fast (gridDim.x = 4) so adjacent CTAs share the same A tile in L2.
// ---------------------------------------------------------------------------
#define BM 256
#define BN 128
#define GPITCH 264    // 256 + 8 bf16 padding -> conflict-free 32-bit LDS

__global__ void __launch_bounds__(512) gemm_bf16_kernel(
        const float* __restrict__ x, const float* __restrict__ w) {
    extern __shared__ __nv_bfloat16 smem[];
    __nv_bfloat16* sA = smem;                  // BM * GPITCH
    __nv_bfloat16* sB = smem + BM * GPITCH;    // BN * GPITCH

    const int tid = threadIdx.x;
    const long tileM = (long)blockIdx.y * BM;
    const int  tileN = blockIdx.x * BN;

    // Stage A: 256x256 fp32 -> bf16  (65536 elems, 128 float4/thread-iter)
#pragma unroll
    for (int i = 0; i < 32; ++i) {
        int idx = tid + i * 512;              // 0 .. 16383 (float4 units)
        int r = idx >> 6;                     // row 0..255
        int c4 = idx & 63;                    // float4-col 0..63
        float4 v = *reinterpret_cast<const float4*>(x + (tileM + r) * NIN + c4 * 4);
        __nv_bfloat162 lo = __floats2bfloat162_rn(v.x, v.y);
        __nv_bfloat162 hi = __floats2bfloat162_rn(v.z, v.w);
        __nv_bfloat162* dst =
            reinterpret_cast<__nv_bfloat162*>(sA + r * GPITCH + c4 * 4);
        dst[0] = lo; dst[1] = hi;
    }
    // Stage B: 128x256 fp32 -> bf16
#pragma unroll
    for (int i = 0; i < 16; ++i) {
        int idx = tid + i * 512;              // 0 .. 8191
        int r = idx >> 6;
        int c4 = idx & 63;
        float4 v = *reinterpret_cast<const float4*>(w + (long)(tileN + r) * NIN + c4 * 4);
        __nv_bfloat162 lo = __floats2bfloat162_rn(v.x, v.y);
        __nv_bfloat162 hi = __floats2bfloat162_rn(v.z, v.w);
        __nv_bfloat162* dst =
            reinterpret_cast<__nv_bfloat162*>(sB + r * GPITCH + c4 * 4);
        dst[0] = lo; dst[1] = hi;
    }
    __syncthreads();

    const int warp = tid >> 5, lane = tid & 31;
    const int wm = warp & 3;        // 0..3  (64-row slabs)
    const int wn = warp >> 2;       // 0..3  (32-col slabs)
    const int g  = lane >> 2;       // group id 0..7
    const int tg = lane & 3;        // thread-in-group 0..3

    const __nv_bfloat16* wA = sA + (wm * 64 + g) * GPITCH + tg * 2;
    const __nv_bfloat16* wB = sB + (wn * 32 + g) * GPITCH + tg * 2;

    float acc[4][4][4];
#pragma unroll
    for (int a = 0; a < 4; ++a)
#pragma unroll
        for (int b = 0; b < 4; ++b)
#pragma unroll
            for (int c = 0; c < 4; ++c) acc[a][b][c] = 0.f;

#pragma unroll
    for (int ks = 0; ks < 16; ++ks) {
        const int k0 = ks * 16;
        uint32_t af[4][4], bfr[4][2];
#pragma unroll
        for (int mt = 0; mt < 4; ++mt) {
            const __nv_bfloat16* p = wA + mt * 16 * GPITCH + k0;
            af[mt][0] = *reinterpret_cast<const uint32_t*>(p);
            af[mt][1] = *reinterpret_cast<const uint32_t*>(p + 8 * GPITCH);
            af[mt][2] = *reinterpret_cast<const uint32_t*>(p + 8);
            af[mt][3] = *reinterpret_cast<const uint32_t*>(p + 8 * GPITCH + 8);
        }
#pragma unroll
        for (int nt = 0; nt < 4; ++nt) {
            const __nv_bfloat16* p = wB + nt * 8 * GPITCH + k0;
            bfr[nt][0] = *reinterpret_cast<const uint32_t*>(p);
            bfr[nt][1] = *reinterpret_cast<const uint32_t*>(p + 8);
        }
#pragma unroll
        for (int mt = 0; mt < 4; ++mt)
#pragma unroll
            for (int nt = 0; nt < 4; ++nt)
                asm volatile(
                    "mma.sync.aligned.m16n8k16.row.col.f32.bf16.bf16.f32 "
                    "{%0,%1,%2,%3}, {%4,%5,%6,%7}, {%8,%9}, {%0,%1,%2,%3};\n"
                    : "+f"(acc[mt][nt][0]), "+f"(acc[mt][nt][1]),
                      "+f"(acc[mt][nt][2]), "+f"(acc[mt][nt][3])
                    : "r"(af[mt][0]), "r"(af[mt][1]), "r"(af[mt][2]), "r"(af[mt][3]),
                      "r"(bfr[nt][0]), "r"(bfr[nt][1]));
    }

    // Epilogue: bf16 stores
#pragma unroll
    for (int mt = 0; mt < 4; ++mt) {
        long row0 = tileM + wm * 64 + mt * 16 + g;
#pragma unroll
        for (int nt = 0; nt < 4; ++nt) {
            int col = tileN + wn * 32 + nt * 8 + tg * 2;
            *reinterpret_cast<__nv_bfloat162*>(g_xproj + row0 * NHID + col) =
                __floats2bfloat162_rn(acc[mt][nt][0], acc[mt][nt][1]);
            *reinterpret_cast<__nv_bfloat162*>(g_xproj + (row0 + 8) * NHID + col) =
                __floats2bfloat162_rn(acc[mt][nt][2], acc[mt][nt][3]);
        }
    }
}

// ---------------------------------------------------------------------------
// Phase 1: barrier-free speculative scan.
// Until the first spike anywhere, psc = a0 = a1 = 0 exactly, so
//   v' = 0.95*v + (0.5*I - 3.0)
// per neuron, fully decoupled. Track running max of v'; a crossing of V_TH
// under this assumption <=> a spike exists under true dynamics (detection of
// the FIRST crossing is exact). If a crossing occurred, set g_flag; the
// fallback kernel recomputes everything. Rates are zero in the no-spike case.
// 128 CTAs x 128 threads, 2 neurons/thread, depth-16 prefetch.
// ---------------------------------------------------------------------------
#define PF1 16

__global__ void __launch_bounds__(128) scan_fast_kernel() {
    const int tid  = threadIdx.x;
    const int b    = blockIdx.x >> 1;
    const int half = blockIdx.x & 1;
    const int elem = b * NHID + half * 256 + 2 * tid;   // bf16 element offset

    const long stride = (long)BATCH * NHID / 2;          // bf16x2 units per step
    const __nv_bfloat162* __restrict__ xp =
        reinterpret_cast<const __nv_bfloat162*>(g_xproj) + (elem >> 1);

    __nv_bfloat162 buf[PF1];
#pragma unroll
    for (int d = 0; d < PF1; ++d) buf[d] = xp[(long)d * stride];

    float v0 = V_RESET, v1 = V_RESET;
    float m0 = -1e30f,  m1 = -1e30f;

    for (int t = 0; t < T_STEPS; t += PF1) {
#pragma unroll
        for (int d = 0; d < PF1; ++d) {
            float2 I = __bfloat1622float2(buf[d]);
            int tn = t + d + PF1;
            if (tn > T_STEPS - 1) tn = T_STEPS - 1;      // tail never consumed
            buf[d] = xp[(long)tn * stride];

            float c0 = fmaf(DT_CM, I.x, -3.0f);          // 0.5*I - 0.05*60
            float c1 = fmaf(DT_CM, I.y, -3.0f);
            v0 = fmaf(0.95f, v0, c0);
            v1 = fmaf(0.95f, v1, c1);
            m0 = fmaxf(m0, v0);
            m1 = fmaxf(m1, v1);
        }
    }

    int any = (m0 >= V_TH) | (m1 >= V_TH);
    if (__syncthreads_or(any) && tid == 0) atomicOr(&g_flag, 1);

    // Rates: exact zeros when no spike; fallback overwrites otherwise.
    *reinterpret_cast<float2*>(g_rate + elem) = make_float2(0.f, 0.f);
}

// ---------------------------------------------------------------------------
// Fallback: full coupled simulation (validated R2 logic, bf16 input).
// Early-returns when no spike was detected. 64 CTAs, 128 threads, 4 n/thread.
// ---------------------------------------------------------------------------
#define PF2 8

__global__ void __launch_bounds__(128) scan_full_kernel() {
    if (g_flag == 0) return;

    const int b = blockIdx.x;
    const int tid = threadIdx.x;          // neurons 4*tid .. 4*tid+3

    __shared__ unsigned s_mask[16];

    float v[4], a0[4], a1[4], psc[4], cnt[4];
#pragma unroll
    for (int i = 0; i < 4; ++i) {
        v[i] = V_RESET; a0[i] = 0.f; a1[i] = 0.f; psc[i] = 0.f; cnt[i] = 0.f;
    }

    const long stride = (long)BATCH * NHID / 4;   // uint2 (4 bf16) units
    const uint2* __restrict__ xp =
        reinterpret_cast<const uint2*>(g_xproj) + (long)b * (NHID / 4) + tid;

    uint2 buf[PF2];
#pragma unroll
    for (int d = 0; d < PF2; ++d) buf[d] = xp[(long)d * stride];

    for (int t = 0; t < T_STEPS; t += PF2) {
#pragma unroll
        for (int d = 0; d < PF2; ++d) {
            uint2 raw = buf[d];
            int tn = t + d + PF2;
            if (tn > T_STEPS - 1) tn = T_STEPS - 1;
            buf[d] = xp[(long)tn * stride];

            float2 lo = __bfloat1622float2(*reinterpret_cast<__nv_bfloat162*>(&raw.x));
            float2 hi = __bfloat1622float2(*reinterpret_cast<__nv_bfloat162*>(&raw.y));
            float Ii[4] = {lo.x, lo.y, hi.x, hi.y};
            bool sp[4];
#pragma unroll
            for (int i = 0; i < 4; ++i) {
                float Itot  = Ii[i] + psc[i] + a0[i] + a1[i];
                float v_int = v[i] + DT_CM * Itot - DECAY_V * (v[i] - V_RESET);
                sp[i] = v_int >= V_TH;
                v[i]  = sp[i] ? V_RESET : v_int;
                a0[i] = a0[i] * D_ASC0 + (sp[i] ? AMP0 : 0.f);
                a1[i] = a1[i] * D_ASC1 + (sp[i] ? AMP1 : 0.f);
                cnt[i] += sp[i] ? 1.f : 0.f;
            }
            int anyl = (int)(sp[0] | sp[1] | sp[2] | sp[3]);

            if (__syncthreads_or(anyl)) {
                if (tid < 16) s_mask[tid] = 0;
                __syncthreads();
                unsigned nib = (unsigned)sp[0] | ((unsigned)sp[1] << 1)
                             | ((unsigned)sp[2] << 2) | ((unsigned)sp[3] << 3);
                if (nib) atomicOr(&s_mask[tid >> 3], nib << (4 * (tid & 7)));
                __syncthreads();
                float rec[4] = {0.f, 0.f, 0.f, 0.f};
#pragma unroll 1
                for (int w = 0; w < 16; ++w) {
                    unsigned word = s_mask[w];
                    while (word) {
                        int j = (w << 5) + __ffs(word) - 1;
                        word &= word - 1;
                        float4 wv = *reinterpret_cast<const float4*>(
                            g_wrecT + j * NHID + 4 * tid);
                        rec[0] += wv.x; rec[1] += wv.y;
                        rec[2] += wv.z; rec[3] += wv.w;
                    }
                }
                __syncthreads();
#pragma unroll
                for (int i = 0; i < 4; ++i) psc[i] = psc[i] * D_SYN + rec[i];
            } else {
#pragma unroll
                for (int i = 0; i < 4; ++i) psc[i] *= D_SYN;
            }
        }
    }

    float4 r = make_float4(cnt[0] * (1.0f / T_STEPS), cnt[1] * (1.0f / T_STEPS),
                           cnt[2] * (1.0f / T_STEPS), cnt[3] * (1.0f / T_STEPS));
    reinterpret_cast<float4*>(g_rate)[b * (NHID / 4) + tid] = r;
}

// ---------------------------------------------------------------------------
// Output: out[b][o] = sum_h rate[b][h] * W_out[o][h]
// ---------------------------------------------------------------------------
__global__ void __launch_bounds__(128) out_kernel(const float* __restrict__ W_out,
                                                  float* __restrict__ out) {
    const int b = blockIdx.x;
    const int o = threadIdx.x;
    __shared__ float sr[NHID];
    for (int i = o; i < NHID; i += 128) sr[i] = g_rate[b * NHID + i];
    __syncthreads();

    float acc = 0.f;
    const float4* w = reinterpret_cast<const float4*>(W_out + o * NHID);
#pragma unroll 4
    for (int i = 0; i < NHID / 4; ++i) {
        float4 wv = w[i];
        acc += wv.x * sr[4 * i] + wv.y * sr[4 * i + 1]
             + wv.z * sr[4 * i + 2] + wv.w * sr[4 * i + 3];
    }
    out[b * NOUT + o] = acc;
}

// ---------------------------------------------------------------------------
// Launch
// ---------------------------------------------------------------------------
extern "C" void kernel_launch(void* const* d_in, const int* in_sizes, int n_in,
                              void* d_out, int out_size) {
    const float* x     = (const float*)d_in[0];   // (1000, 64, 256)
    const float* W_in  = (const float*)d_in[1];   // (512, 256)
    const float* W_rec = (const float*)d_in[2];   // (512, 512)
    const float* W_out = (const float*)d_in[3];   // (128, 512)
    float* out = (float*)d_out;                   // (64, 128)

    (void)in_sizes; (void)n_in; (void)out_size;

    reset_flag_kernel<<<1, 1>>>();
    transpose_wrec_kernel<<<NHID, NHID>>>(W_rec);

    const int smem_bytes = (BM + BN) * GPITCH * (int)sizeof(__nv_bfloat16); // 202752
    cudaFuncSetAttribute(gemm_bf16_kernel,
                         cudaFuncAttributeMaxDynamicSharedMemorySize, smem_bytes);
    gemm_bf16_kernel<<<dim3(NHID / BN, M_ROWS / BM), 512, smem_bytes>>>(x, W_in);

    scan_fast_kernel<<<2 * BATCH, 128>>>();
    scan_full_kernel<<<BATCH, 128>>>();

    out_kernel<<<BATCH, NOUT>>>(W_out, out);
}

// round 4
// speedup vs baseline: 5.6651x; 1.3181x over previous
#include <cuda_runtime.h>
#include <cuda_bf16.h>
#include <cstdint>

// ---------------------------------------------------------------------------
// Problem constants
// ---------------------------------------------------------------------------
#define T_STEPS 1000
#define BATCH   64
#define NIN     256
#define NHID    512
#define NOUT    128
#define M_ROWS  (T_STEPS * BATCH)   // 64000

// GLIF constants
#define V_TH     (-45.0f)
#define V_RESET  (-60.0f)
#define DT_CM    (0.5f)     // DT / C_M
#define DECAY_V  (0.05f)    // DT / TAU
#define D_ASC0   (0.9048374180359595f)   // exp(-0.1)
#define D_ASC1   (0.8187307530779818f)   // exp(-0.2)
#define D_SYN    (0.8187307530779818f)   // exp(-0.2)
#define AMP0     (1.0f)
#define AMP1     (-2.0f)

#define VKEEP    (0.95f)                 // 1 - DT/TAU
#define RINV     (1.0526315789473684f)   // 1/0.95
#define CHUNK    100
#define NCHUNK   10
#define A100     (5.920540e-3f)          // 0.95^100

// ---------------------------------------------------------------------------
// Device scratch (static — no allocation allowed)
// x_proj layout: [b][t][h]  (b*512000 + t*512 + h), bf16
// ---------------------------------------------------------------------------
__device__ __align__(128) __nv_bfloat16 g_xproj[(size_t)M_ROWS * NHID]; // 65.5 MB
__device__ __align__(128) __nv_bfloat16 g_wb[NHID * NIN];               // 256 KB
__device__ __align__(128) float g_wrecT[NHID * NHID];                   // 1 MB
__device__ __align__(128) float g_rate[BATCH * NHID];                   // 128 KB
__device__ __align__(128) float g_chkB[NCHUNK * BATCH * NHID];          // 1.3 MB
__device__ __align__(128) float g_chkT[NCHUNK * BATCH * NHID];          // 1.3 MB
__device__ int g_bspike[BATCH];

// ---------------------------------------------------------------------------
// Convert W_in (fp32) -> bf16
// ---------------------------------------------------------------------------
__global__ void cvt_w_kernel(const float4* __restrict__ in) {
    int i = blockIdx.x * blockDim.x + threadIdx.x;   // i < 32768
    float4 v = in[i];
    __nv_bfloat162 lo = __floats2bfloat162_rn(v.x, v.y);
    __nv_bfloat162 hi = __floats2bfloat162_rn(v.z, v.w);
    reinterpret_cast<__nv_bfloat162*>(g_wb)[2 * i]     = lo;
    reinterpret_cast<__nv_bfloat162*>(g_wb)[2 * i + 1] = hi;
}

// ---------------------------------------------------------------------------
// Transpose W_rec (512x512): g_wrecT[j][h] = W_rec[h][j] (fallback only)
// ---------------------------------------------------------------------------
__global__ void transpose_wrec_kernel(const float* __restrict__ w) {
    int j = blockIdx.x;
    int h = threadIdx.x;
    g_wrecT[j * NHID + h] = w[h * NHID + j];
}

// ---------------------------------------------------------------------------
// GEMM v3: x_proj = x @ W_in^T. BM=128, BN=256, K=256 in 8 chunks of 32.
// Double-buffered smem (2 x 30KB); global loads of chunk k+1 (regs) overlap
// mma of chunk k. 512 threads = 16 warps (2m x 8n), warp tile 64x32.
// A (x) read fp32 + inline cvt; B from pre-converted g_wb (bf16).
// Epilogue permutes rows to [b][t][h] layout, bf16 stores.
// ---------------------------------------------------------------------------
#define BMg 128
#define BNg 256
#define KC  32
#define NCH 8
#define GP  40          // 32 + 8 pad (elems) -> conflict-free 32-bit LDS
#define ABUF (BMg * GP)             // 5120 elems
#define BUFE (ABUF + BNg * GP)      // 15360 elems per stage

__global__ void __launch_bounds__(512) gemm_bf16_kernel(const float* __restrict__ x) {
    extern __shared__ __nv_bfloat16 smem[];   // 2 * BUFE elems = 61440 B

    const int tid = threadIdx.x;
    const long tileM = (long)blockIdx.y * BMg;
    const int  tileN = blockIdx.x * BNg;

    const int warp = tid >> 5, lane = tid & 31;
    const int wm = warp & 1;        // 0..1  (64-row slabs)
    const int wn = warp >> 1;       // 0..7  (32-col slabs)
    const int g  = lane >> 2;       // 0..7
    const int tg = lane & 3;        // 0..3

    // ---- staging helpers (per chunk): A 1024 float4, B 1024 uint4 ----
    float4 bufA[2];
    uint4  bufB[2];

    auto load_chunk = [&](int kc) {
        const int k0 = kc * KC;
#pragma unroll
        for (int i = 0; i < 2; ++i) {
            int idx = tid + i * 512;
            {   // A: r = idx>>3 (128 rows, 8 float4/row), c4 = idx&7
                int r = idx >> 3, c4 = idx & 7;
                bufA[i] = *reinterpret_cast<const float4*>(
                    x + (tileM + r) * NIN + k0 + c4 * 4);
            }
            {   // B: r = idx>>2 (256 rows, 4 uint4/row), c8 = idx&3
                int r = idx >> 2, c8 = idx & 3;
                bufB[i] = *reinterpret_cast<const uint4*>(
                    g_wb + (long)(tileN + r) * NIN + k0 + c8 * 8);
            }
        }
    };
    auto store_chunk = [&](int p) {
        __nv_bfloat16* sA = smem + p * BUFE;
        __nv_bfloat16* sB = smem + p * BUFE + ABUF;
#pragma unroll
        for (int i = 0; i < 2; ++i) {
            int idx = tid + i * 512;
            {
                int r = idx >> 3, c4 = idx & 7;
                float4 v = bufA[i];
                __nv_bfloat162 lo = __floats2bfloat162_rn(v.x, v.y);
                __nv_bfloat162 hi = __floats2bfloat162_rn(v.z, v.w);
                __nv_bfloat162* dst =
                    reinterpret_cast<__nv_bfloat162*>(sA + r * GP + c4 * 4);
                dst[0] = lo; dst[1] = hi;
            }
            {
                int r = idx >> 2, c8 = idx & 3;
                *reinterpret_cast<uint4*>(sB + r * GP + c8 * 8) = bufB[i];
            }
        }
    };

    float acc[4][4][4];
#pragma unroll
    for (int a = 0; a < 4; ++a)
#pragma unroll
        for (int b = 0; b < 4; ++b)
#pragma unroll
            for (int c = 0; c < 4; ++c) acc[a][b][c] = 0.f;

    load_chunk(0);
    store_chunk(0);
    __syncthreads();

    int p = 0;
    for (int kc = 0; kc < NCH; ++kc) {
        if (kc + 1 < NCH) load_chunk(kc + 1);

        const __nv_bfloat16* wA = smem + p * BUFE + (wm * 64 + g) * GP + tg * 2;
        const __nv_bfloat16* wB = smem + p * BUFE + ABUF + (wn * 32 + g) * GP + tg * 2;

#pragma unroll
        for (int ks = 0; ks < 2; ++ks) {
            const int k0 = ks * 16;
            uint32_t af[4][4], bfr[4][2];
#pragma unroll
            for (int mt = 0; mt < 4; ++mt) {
                const __nv_bfloat16* pp = wA + mt * 16 * GP + k0;
                af[mt][0] = *reinterpret_cast<const uint32_t*>(pp);
                af[mt][1] = *reinterpret_cast<const uint32_t*>(pp + 8 * GP);
                af[mt][2] = *reinterpret_cast<const uint32_t*>(pp + 8);
                af[mt][3] = *reinterpret_cast<const uint32_t*>(pp + 8 * GP + 8);
            }
#pragma unroll
            for (int nt = 0; nt < 4; ++nt) {
                const __nv_bfloat16* pp = wB + nt * 8 * GP + k0;
                bfr[nt][0] = *reinterpret_cast<const uint32_t*>(pp);
                bfr[nt][1] = *reinterpret_cast<const uint32_t*>(pp + 8);
            }
#pragma unroll
            for (int mt = 0; mt < 4; ++mt)
#pragma unroll
                for (int nt = 0; nt < 4; ++nt)
                    asm volatile(
                        "mma.sync.aligned.m16n8k16.row.col.f32.bf16.bf16.f32 "
                        "{%0,%1,%2,%3}, {%4,%5,%6,%7}, {%8,%9}, {%0,%1,%2,%3};\n"
                        : "+f"(acc[mt][nt][0]), "+f"(acc[mt][nt][1]),
                          "+f"(acc[mt][nt][2]), "+f"(acc[mt][nt][3])
                        : "r"(af[mt][0]), "r"(af[mt][1]), "r"(af[mt][2]), "r"(af[mt][3]),
                          "r"(bfr[nt][0]), "r"(bfr[nt][1]));
        }

        if (kc + 1 < NCH) {
            store_chunk(1 - p);
            __syncthreads();
            p ^= 1;
        }
    }

    // Epilogue: permuted rows -> [b][t][h]
#pragma unroll
    for (int mt = 0; mt < 4; ++mt) {
        long m0 = tileM + wm * 64 + mt * 16 + g;
        long b0 = m0 & 63, t0 = m0 >> 6;
        long m1 = m0 + 8;
        long b1 = m1 & 63, t1 = m1 >> 6;
        __nv_bfloat16* d0 = g_xproj + (b0 * T_STEPS + t0) * NHID;
        __nv_bfloat16* d1 = g_xproj + (b1 * T_STEPS + t1) * NHID;
#pragma unroll
        for (int nt = 0; nt < 4; ++nt) {
            int col = tileN + wn * 32 + nt * 8 + tg * 2;
            *reinterpret_cast<__nv_bfloat162*>(d0 + col) =
                __floats2bfloat162_rn(acc[mt][nt][0], acc[mt][nt][1]);
            *reinterpret_cast<__nv_bfloat162*>(d1 + col) =
                __floats2bfloat162_rn(acc[mt][nt][2], acc[mt][nt][3]);
        }
    }
}

// ---------------------------------------------------------------------------
// Scan phase A: chunked affine summaries, barrier-free, 10x parallel in t.
// Pre-first-spike dynamics are linear: v(k) = 0.95^k * v_in + D_k with
//   D_k = 0.95*D_{k-1} + (0.5*I - 3).
// Crossing in chunk  <=>  v_in >= theta = min_k (V_TH - D_k) * 0.95^{-k}.
// Each CTA = (batch b, chunk c): 128 threads x 4 neurons, uint2 (4xbf16)
// loads, depth-10 prefetch. Writes (D_100, theta) per neuron.
// ---------------------------------------------------------------------------
__global__ void __launch_bounds__(128) scanA_kernel() {
    const int tid = threadIdx.x;
    const int b = blockIdx.x & 63;
    const int c = blockIdx.x >> 6;          // 0..9
    const int t0g = c * CHUNK;

    const uint2* __restrict__ xp =
        reinterpret_cast<const uint2*>(g_xproj) + (long)b * (T_STEPS * NHID / 4) + tid;

    uint2 buf[10];
#pragma unroll
    for (int d = 0; d < 10; ++d) buf[d] = xp[(long)(t0g + d) * (NHID / 4)];

    float D[4]  = {0.f, 0.f, 0.f, 0.f};
    float th[4] = {1e30f, 1e30f, 1e30f, 1e30f};
    float invp  = 1.f;

    for (int tt = 0; tt < CHUNK; tt += 10) {
#pragma unroll
        for (int d = 0; d < 10; ++d) {
            uint2 raw = buf[d];
            int tp = t0g + tt + d + 10;
            if (tp > T_STEPS - 1) tp = T_STEPS - 1;      // tail never consumed
            buf[d] = xp[(long)tp * (NHID / 4)];

            float2 lo = __bfloat1622float2(*reinterpret_cast<__nv_bfloat162*>(&raw.x));
            float2 hi = __bfloat1622float2(*reinterpret_cast<__nv_bfloat162*>(&raw.y));
            float I[4] = {lo.x, lo.y, hi.x, hi.y};

            invp *= RINV;
#pragma unroll
            for (int i = 0; i < 4; ++i) {
                float cc = fmaf(DT_CM, I[i], -3.0f);     // 0.5*I - 0.05*60
                D[i] = fmaf(VKEEP, D[i], cc);
                th[i] = fminf(th[i], (V_TH - D[i]) * invp);
            }
        }
    }

    const long base = ((long)c * BATCH + b) * NHID + 4 * tid;
    *reinterpret_cast<float4*>(g_chkB + base) = make_float4(D[0], D[1], D[2], D[3]);
    *reinterpret_cast<float4*>(g_chkT + base) = make_float4(th[0], th[1], th[2], th[3]);
}

// ---------------------------------------------------------------------------
// Scan phase B: combine 10 chunk summaries per neuron, per-batch spike flag,
// zero rates (exact when spike-free). Written unconditionally every replay
// -> no reset kernel needed.
// ---------------------------------------------------------------------------
__global__ void __launch_bounds__(512) scanB_kernel() {
    const int b = blockIdx.x;
    const int h = threadIdx.x;

    float v = V_RESET;
    int sp = 0;
#pragma unroll
    for (int c = 0; c < NCHUNK; ++c) {
        long idx = ((long)c * BATCH + b) * NHID + h;
        float th = g_chkT[idx];
        float Bd = g_chkB[idx];
        sp |= (v >= th);
        v = fmaf(A100, v, Bd);
    }

    int any = __syncthreads_or(sp);
    if (h == 0) g_bspike[b] = any;
    g_rate[b * NHID + h] = 0.f;
}

// ---------------------------------------------------------------------------
// Fallback: full coupled simulation (per-batch; runs only if batch spiked).
// 64 CTAs, 128 threads, 4 neurons/thread, [b][t][h] layout.
// ---------------------------------------------------------------------------
#define PF2 8

__global__ void __launch_bounds__(128) scan_full_kernel() {
    const int b = blockIdx.x;
    if (g_bspike[b] == 0) return;

    const int tid = threadIdx.x;          // neurons 4*tid .. 4*tid+3

    __shared__ unsigned s_mask[16];

    float v[4], a0[4], a1[4], psc[4], cnt[4];
#pragma unroll
    for (int i = 0; i < 4; ++i) {
        v[i] = V_RESET; a0[i] = 0.f; a1[i] = 0.f; psc[i] = 0.f; cnt[i] = 0.f;
    }

    const uint2* __restrict__ xp =
        reinterpret_cast<const uint2*>(g_xproj) + (long)b * (T_STEPS * NHID / 4) + tid;

    uint2 buf[PF2];
#pragma unroll
    for (int d = 0; d < PF2; ++d) buf[d] = xp[(long)d * (NHID / 4)];

    for (int t = 0; t < T_STEPS; t += PF2) {
#pragma unroll
        for (int d = 0; d < PF2; ++d) {
            uint2 raw = buf[d];
            int tn = t + d + PF2;
            if (tn > T_STEPS - 1) tn = T_STEPS - 1;
            buf[d] = xp[(long)tn * (NHID / 4)];

            float2 lo = __bfloat1622float2(*reinterpret_cast<__nv_bfloat162*>(&raw.x));
            float2 hi = __bfloat1622float2(*reinterpret_cast<__nv_bfloat162*>(&raw.y));
            float Ii[4] = {lo.x, lo.y, hi.x, hi.y};
            bool sp[4];
#pragma unroll
            for (int i = 0; i < 4; ++i) {
                float Itot  = Ii[i] + psc[i] + a0[i] + a1[i];
                float v_int = v[i] + DT_CM * Itot - DECAY_V * (v[i] - V_RESET);
                sp[i] = v_int >= V_TH;
                v[i]  = sp[i] ? V_RESET : v_int;
                a0[i] = a0[i] * D_ASC0 + (sp[i] ? AMP0 : 0.f);
                a1[i] = a1[i] * D_ASC1 + (sp[i] ? AMP1 : 0.f);
                cnt[i] += sp[i] ? 1.f : 0.f;
            }
            int anyl = (int)(sp[0] | sp[1] | sp[2] | sp[3]);

            if (__syncthreads_or(anyl)) {
                if (tid < 16) s_mask[tid] = 0;
                __syncthreads();
                unsigned nib = (unsigned)sp[0] | ((unsigned)sp[1] << 1)
                             | ((unsigned)sp[2] << 2) | ((unsigned)sp[3] << 3);
                if (nib) atomicOr(&s_mask[tid >> 3], nib << (4 * (tid & 7)));
                __syncthreads();
                float rec[4] = {0.f, 0.f, 0.f, 0.f};
#pragma unroll 1
                for (int w = 0; w < 16; ++w) {
                    unsigned word = s_mask[w];
                    while (word) {
                        int j = (w << 5) + __ffs(word) - 1;
                        word &= word - 1;
                        float4 wv = *reinterpret_cast<const float4*>(
                            g_wrecT + j * NHID + 4 * tid);
                        rec[0] += wv.x; rec[1] += wv.y;
                        rec[2] += wv.z; rec[3] += wv.w;
                    }
                }
                __syncthreads();
#pragma unroll
                for (int i = 0; i < 4; ++i) psc[i] = psc[i] * D_SYN + rec[i];
            } else {
#pragma unroll
                for (int i = 0; i < 4; ++i) psc[i] *= D_SYN;
            }
        }
    }

    float4 r = make_float4(cnt[0] * (1.0f / T_STEPS), cnt[1] * (1.0f / T_STEPS),
                           cnt[2] * (1.0f / T_STEPS), cnt[3] * (1.0f / T_STEPS));
    reinterpret_cast<float4*>(g_rate)[b * (NHID / 4) + tid] = r;
}

// ---------------------------------------------------------------------------
// Output: out[b][o] = sum_h rate[b][h] * W_out[o][h]
// ---------------------------------------------------------------------------
__global__ void __launch_bounds__(128) out_kernel(const float* __restrict__ W_out,
                                                  float* __restrict__ out) {
    const int b = blockIdx.x;
    const int o = threadIdx.x;
    __shared__ float sr[NHID];
    for (int i = o; i < NHID; i += 128) sr[i] = g_rate[b * NHID + i];
    __syncthreads();

    float acc = 0.f;
    const float4* w = reinterpret_cast<const float4*>(W_out + o * NHID);
#pragma unroll 4
    for (int i = 0; i < NHID / 4; ++i) {
        float4 wv = w[i];
        acc += wv.x * sr[4 * i] + wv.y * sr[4 * i + 1]
             + wv.z * sr[4 * i + 2] + wv.w * sr[4 * i + 3];
    }
    out[b * NOUT + o] = acc;
}

// ---------------------------------------------------------------------------
// Launch
// ---------------------------------------------------------------------------
extern "C" void kernel_launch(void* const* d_in, const int* in_sizes, int n_in,
                              void* d_out, int out_size) {
    const float* x     = (const float*)d_in[0];   // (1000, 64, 256)
    const float* W_in  = (const float*)d_in[1];   // (512, 256)
    const float* W_rec = (const float*)d_in[2];   // (512, 512)
    const float* W_out = (const float*)d_in[3];   // (128, 512)
    float* out = (float*)d_out;                   // (64, 128)

    (void)in_sizes; (void)n_in; (void)out_size;

    cvt_w_kernel<<<128, 256>>>(reinterpret_cast<const float4*>(W_in));
    transpose_wrec_kernel<<<NHID, NHID>>>(W_rec);

    const int smem_bytes = 2 * BUFE * (int)sizeof(__nv_bfloat16);  // 61440
    cudaFuncSetAttribute(gemm_bf16_kernel,
                         cudaFuncAttributeMaxDynamicSharedMemorySize, smem_bytes);
    gemm_bf16_kernel<<<dim3(NHID / BNg, M_ROWS / BMg), 512, smem_bytes>>>(x);

    scanA_kernel<<<NCHUNK * BATCH, 128>>>();
    scanB_kernel<<<BATCH, 512>>>();
    scan_full_kernel<<<BATCH, 128>>>();

    out_kernel<<<BATCH, NOUT>>>(W_out, out);
}

// round 5
// speedup vs baseline: 5.6664x; 1.0002x over previous
#include <cuda_runtime.h>
#include <cuda_bf16.h>
#include <cstdint>

// ---------------------------------------------------------------------------
// Problem constants
// ---------------------------------------------------------------------------
#define T_STEPS 1000
#define BATCH   64
#define NIN     256
#define NHID    512
#define NOUT    128
#define M_ROWS  (T_STEPS * BATCH)   // 64000

// GLIF constants
#define V_TH     (-45.0f)
#define V_RESET  (-60.0f)
#define DT_CM    (0.5f)     // DT / C_M
#define DECAY_V  (0.05f)    // DT / TAU
#define D_ASC0   (0.9048374180359595f)   // exp(-0.1)
#define D_ASC1   (0.8187307530779818f)   // exp(-0.2)
#define D_SYN    (0.8187307530779818f)   // exp(-0.2)
#define AMP0     (1.0f)
#define AMP1     (-2.0f)

#define VKEEP    (0.95f)                 // 1 - DT/TAU
#define RINV     (1.0526315789473684f)   // 1/0.95
#define CHUNK    100
#define NCHUNK   10
#define A100     (5.920540e-3f)          // 0.95^100

// ---------------------------------------------------------------------------
// Device scratch (static — no allocation allowed)
// x_proj layout: [b][t][h]  (b*512000 + t*512 + h), bf16
// ---------------------------------------------------------------------------
__device__ __align__(128) __nv_bfloat16 g_xproj[(size_t)M_ROWS * NHID]; // 65.5 MB
__device__ __align__(128) __nv_bfloat16 g_wb[NHID * NIN];               // 256 KB
__device__ __align__(128) float g_wrecT[NHID * NHID];                   // 1 MB
__device__ __align__(128) float g_rate[BATCH * NHID];                   // 128 KB
__device__ __align__(128) float g_chkB[NCHUNK * BATCH * NHID];          // 1.3 MB
__device__ __align__(128) float g_chkT[NCHUNK * BATCH * NHID];          // 1.3 MB
__device__ int g_bspike[BATCH];

// ---------------------------------------------------------------------------
// Convert W_in (fp32) -> bf16
// ---------------------------------------------------------------------------
__global__ void cvt_w_kernel(const float4* __restrict__ in) {
    int i = blockIdx.x * blockDim.x + threadIdx.x;   // i < 32768
    float4 v = in[i];
    __nv_bfloat162 lo = __floats2bfloat162_rn(v.x, v.y);
    __nv_bfloat162 hi = __floats2bfloat162_rn(v.z, v.w);
    reinterpret_cast<__nv_bfloat162*>(g_wb)[2 * i]     = lo;
    reinterpret_cast<__nv_bfloat162*>(g_wb)[2 * i + 1] = hi;
}

// ---------------------------------------------------------------------------
// Transpose W_rec (512x512): g_wrecT[j][h] = W_rec[h][j] (fallback only)
// ---------------------------------------------------------------------------
__global__ void transpose_wrec_kernel(const float* __restrict__ w) {
    int j = blockIdx.x;
    int h = threadIdx.x;
    g_wrecT[j * NHID + h] = w[h * NHID + j];
}

// ---------------------------------------------------------------------------
// GEMM v3: x_proj = x @ W_in^T. BM=128, BN=256, K=256 in 8 chunks of 32.
// Double-buffered smem (2 x 30KB); global loads of chunk k+1 (regs) overlap
// mma of chunk k. 512 threads = 16 warps (2m x 8n), warp tile 64x32.
// A (x) read fp32 + inline cvt; B from pre-converted g_wb (bf16).
// Epilogue permutes rows to [b][t][h] layout, bf16 stores.
// ---------------------------------------------------------------------------
#define BMg 128
#define BNg 256
#define KC  32
#define NCH 8
#define GP  40          // 32 + 8 pad (elems) -> conflict-free 32-bit LDS
#define ABUF (BMg * GP)             // 5120 elems
#define BUFE (ABUF + BNg * GP)      // 15360 elems per stage

__global__ void __launch_bounds__(512) gemm_bf16_kernel(const float* __restrict__ x) {
    extern __shared__ __nv_bfloat16 smem[];   // 2 * BUFE elems = 61440 B

    const int tid = threadIdx.x;
    const long tileM = (long)blockIdx.y * BMg;
    const int  tileN = blockIdx.x * BNg;

    const int warp = tid >> 5, lane = tid & 31;
    const int wm = warp & 1;        // 0..1  (64-row slabs)
    const int wn = warp >> 1;       // 0..7  (32-col slabs)
    const int g  = lane >> 2;       // 0..7
    const int tg = lane & 3;        // 0..3

    // ---- staging helpers (per chunk): A 1024 float4, B 1024 uint4 ----
    float4 bufA[2];
    uint4  bufB[2];

    auto load_chunk = [&](int kc) {
        const int k0 = kc * KC;
#pragma unroll
        for (int i = 0; i < 2; ++i) {
            int idx = tid + i * 512;
            {   // A: r = idx>>3 (128 rows, 8 float4/row), c4 = idx&7
                int r = idx >> 3, c4 = idx & 7;
                bufA[i] = *reinterpret_cast<const float4*>(
                    x + (tileM + r) * NIN + k0 + c4 * 4);
            }
            {   // B: r = idx>>2 (256 rows, 4 uint4/row), c8 = idx&3
                int r = idx >> 2, c8 = idx & 3;
                bufB[i] = *reinterpret_cast<const uint4*>(
                    g_wb + (long)(tileN + r) * NIN + k0 + c8 * 8);
            }
        }
    };
    auto store_chunk = [&](int p) {
        __nv_bfloat16* sA = smem + p * BUFE;
        __nv_bfloat16* sB = smem + p * BUFE + ABUF;
#pragma unroll
        for (int i = 0; i < 2; ++i) {
            int idx = tid + i * 512;
            {
                int r = idx >> 3, c4 = idx & 7;
                float4 v = bufA[i];
                __nv_bfloat162 lo = __floats2bfloat162_rn(v.x, v.y);
                __nv_bfloat162 hi = __floats2bfloat162_rn(v.z, v.w);
                __nv_bfloat162* dst =
                    reinterpret_cast<__nv_bfloat162*>(sA + r * GP + c4 * 4);
                dst[0] = lo; dst[1] = hi;
            }
            {
                int r = idx >> 2, c8 = idx & 3;
                *reinterpret_cast<uint4*>(sB + r * GP + c8 * 8) = bufB[i];
            }
        }
    };

    float acc[4][4][4];
#pragma unroll
    for (int a = 0; a < 4; ++a)
#pragma unroll
        for (int b = 0; b < 4; ++b)
#pragma unroll
            for (int c = 0; c < 4; ++c) acc[a][b][c] = 0.f;

    load_chunk(0);
    store_chunk(0);
    __syncthreads();

    int p = 0;
    for (int kc = 0; kc < NCH; ++kc) {
        if (kc + 1 < NCH) load_chunk(kc + 1);

        const __nv_bfloat16* wA = smem + p * BUFE + (wm * 64 + g) * GP + tg * 2;
        const __nv_bfloat16* wB = smem + p * BUFE + ABUF + (wn * 32 + g) * GP + tg * 2;

#pragma unroll
        for (int ks = 0; ks < 2; ++ks) {
            const int k0 = ks * 16;
            uint32_t af[4][4], bfr[4][2];
#pragma unroll
            for (int mt = 0; mt < 4; ++mt) {
                const __nv_bfloat16* pp = wA + mt * 16 * GP + k0;
                af[mt][0] = *reinterpret_cast<const uint32_t*>(pp);
                af[mt][1] = *reinterpret_cast<const uint32_t*>(pp + 8 * GP);
                af[mt][2] = *reinterpret_cast<const uint32_t*>(pp + 8);
                af[mt][3] = *reinterpret_cast<const uint32_t*>(pp + 8 * GP + 8);
            }
#pragma unroll
            for (int nt = 0; nt < 4; ++nt) {
                const __nv_bfloat16* pp = wB + nt * 8 * GP + k0;
                bfr[nt][0] = *reinterpret_cast<const uint32_t*>(pp);
                bfr[nt][1] = *reinterpret_cast<const uint32_t*>(pp + 8);
            }
#pragma unroll
            for (int mt = 0; mt < 4; ++mt)
#pragma unroll
                for (int nt = 0; nt < 4; ++nt)
                    asm volatile(
                        "mma.sync.aligned.m16n8k16.row.col.f32.bf16.bf16.f32 "
                        "{%0,%1,%2,%3}, {%4,%5,%6,%7}, {%8,%9}, {%0,%1,%2,%3};\n"
                        : "+f"(acc[mt][nt][0]), "+f"(acc[mt][nt][1]),
                          "+f"(acc[mt][nt][2]), "+f"(acc[mt][nt][3])
                        : "r"(af[mt][0]), "r"(af[mt][1]), "r"(af[mt][2]), "r"(af[mt][3]),
                          "r"(bfr[nt][0]), "r"(bfr[nt][1]));
        }

        if (kc + 1 < NCH) {
            store_chunk(1 - p);
            __syncthreads();
            p ^= 1;
        }
    }

    // Epilogue: permuted rows -> [b][t][h]
#pragma unroll
    for (int mt = 0; mt < 4; ++mt) {
        long m0 = tileM + wm * 64 + mt * 16 + g;
        long b0 = m0 & 63, t0 = m0 >> 6;
        long m1 = m0 + 8;
        long b1 = m1 & 63, t1 = m1 >> 6;
        __nv_bfloat16* d0 = g_xproj + (b0 * T_STEPS + t0) * NHID;
        __nv_bfloat16* d1 = g_xproj + (b1 * T_STEPS + t1) * NHID;
#pragma unroll
        for (int nt = 0; nt < 4; ++nt) {
            int col = tileN + wn * 32 + nt * 8 + tg * 2;
            *reinterpret_cast<__nv_bfloat162*>(d0 + col) =
                __floats2bfloat162_rn(acc[mt][nt][0], acc[mt][nt][1]);
            *reinterpret_cast<__nv_bfloat162*>(d1 + col) =
                __floats2bfloat162_rn(acc[mt][nt][2], acc[mt][nt][3]);
        }
    }
}

// ---------------------------------------------------------------------------
// Scan phase A: chunked affine summaries, barrier-free, 10x parallel in t.
// Pre-first-spike dynamics are linear: v(k) = 0.95^k * v_in + D_k with
//   D_k = 0.95*D_{k-1} + (0.5*I - 3).
// Crossing in chunk  <=>  v_in >= theta = min_k (V_TH - D_k) * 0.95^{-k}.
// Each CTA = (batch b, chunk c): 128 threads x 4 neurons, uint2 (4xbf16)
// loads, depth-10 prefetch. Writes (D_100, theta) per neuron.
// ---------------------------------------------------------------------------
__global__ void __launch_bounds__(128) scanA_kernel() {
    const int tid = threadIdx.x;
    const int b = blockIdx.x & 63;
    const int c = blockIdx.x >> 6;          // 0..9
    const int t0g = c * CHUNK;

    const uint2* __restrict__ xp =
        reinterpret_cast<const uint2*>(g_xproj) + (long)b * (T_STEPS * NHID / 4) + tid;

    uint2 buf[10];
#pragma unroll
    for (int d = 0; d < 10; ++d) buf[d] = xp[(long)(t0g + d) * (NHID / 4)];

    float D[4]  = {0.f, 0.f, 0.f, 0.f};
    float th[4] = {1e30f, 1e30f, 1e30f, 1e30f};
    float invp  = 1.f;

    for (int tt = 0; tt < CHUNK; tt += 10) {
#pragma unroll
        for (int d = 0; d < 10; ++d) {
            uint2 raw = buf[d];
            int tp = t0g + tt + d + 10;
            if (tp > T_STEPS - 1) tp = T_STEPS - 1;      // tail never consumed
            buf[d] = xp[(long)tp * (NHID / 4)];

            float2 lo = __bfloat1622float2(*reinterpret_cast<__nv_bfloat162*>(&raw.x));
            float2 hi = __bfloat1622float2(*reinterpret_cast<__nv_bfloat162*>(&raw.y));
            float I[4] = {lo.x, lo.y, hi.x, hi.y};

            invp *= RINV;
#pragma unroll
            for (int i = 0; i < 4; ++i) {
                float cc = fmaf(DT_CM, I[i], -3.0f);     // 0.5*I - 0.05*60
                D[i] = fmaf(VKEEP, D[i], cc);
                th[i] = fminf(th[i], (V_TH - D[i]) * invp);
            }
        }
    }

    const long base = ((long)c * BATCH + b) * NHID + 4 * tid;
    *reinterpret_cast<float4*>(g_chkB + base) = make_float4(D[0], D[1], D[2], D[3]);
    *reinterpret_cast<float4*>(g_chkT + base) = make_float4(th[0], th[1], th[2], th[3]);
}

// ---------------------------------------------------------------------------
// Scan phase B: combine 10 chunk summaries per neuron, per-batch spike flag,
// zero rates (exact when spike-free). Written unconditionally every replay
// -> no reset kernel needed.
// ---------------------------------------------------------------------------
__global__ void __launch_bounds__(512) scanB_kernel() {
    const int b = blockIdx.x;
    const int h = threadIdx.x;

    float v = V_RESET;
    int sp = 0;
#pragma unroll
    for (int c = 0; c < NCHUNK; ++c) {
        long idx = ((long)c * BATCH + b) * NHID + h;
        float th = g_chkT[idx];
        float Bd = g_chkB[idx];
        sp |= (v >= th);
        v = fmaf(A100, v, Bd);
    }

    int any = __syncthreads_or(sp);
    if (h == 0) g_bspike[b] = any;
    g_rate[b * NHID + h] = 0.f;
}

// ---------------------------------------------------------------------------
// Fallback: full coupled simulation (per-batch; runs only if batch spiked).
// 64 CTAs, 128 threads, 4 neurons/thread, [b][t][h] layout.
// ---------------------------------------------------------------------------
#define PF2 8

__global__ void __launch_bounds__(128) scan_full_kernel() {
    const int b = blockIdx.x;
    if (g_bspike[b] == 0) return;

    const int tid = threadIdx.x;          // neurons 4*tid .. 4*tid+3

    __shared__ unsigned s_mask[16];

    float v[4], a0[4], a1[4], psc[4], cnt[4];
#pragma unroll
    for (int i = 0; i < 4; ++i) {
        v[i] = V_RESET; a0[i] = 0.f; a1[i] = 0.f; psc[i] = 0.f; cnt[i] = 0.f;
    }

    const uint2* __restrict__ xp =
        reinterpret_cast<const uint2*>(g_xproj) + (long)b * (T_STEPS * NHID / 4) + tid;

    uint2 buf[PF2];
#pragma unroll
    for (int d = 0; d < PF2; ++d) buf[d] = xp[(long)d * (NHID / 4)];

    for (int t = 0; t < T_STEPS; t += PF2) {
#pragma unroll
        for (int d = 0; d < PF2; ++d) {
            uint2 raw = buf[d];
            int tn = t + d + PF2;
            if (tn > T_STEPS - 1) tn = T_STEPS - 1;
            buf[d] = xp[(long)tn * (NHID / 4)];

            float2 lo = __bfloat1622float2(*reinterpret_cast<__nv_bfloat162*>(&raw.x));
            float2 hi = __bfloat1622float2(*reinterpret_cast<__nv_bfloat162*>(&raw.y));
            float Ii[4] = {lo.x, lo.y, hi.x, hi.y};
            bool sp[4];
#pragma unroll
            for (int i = 0; i < 4; ++i) {
                float Itot  = Ii[i] + psc[i] + a0[i] + a1[i];
                float v_int = v[i] + DT_CM * Itot - DECAY_V * (v[i] - V_RESET);
                sp[i] = v_int >= V_TH;
                v[i]  = sp[i] ? V_RESET : v_int;
                a0[i] = a0[i] * D_ASC0 + (sp[i] ? AMP0 : 0.f);
                a1[i] = a1[i] * D_ASC1 + (sp[i] ? AMP1 : 0.f);
                cnt[i] += sp[i] ? 1.f : 0.f;
            }
            int anyl = (int)(sp[0] | sp[1] | sp[2] | sp[3]);

            if (__syncthreads_or(anyl)) {
                if (tid < 16) s_mask[tid] = 0;
                __syncthreads();
                unsigned nib = (unsigned)sp[0] | ((unsigned)sp[1] << 1)
                             | ((unsigned)sp[2] << 2) | ((unsigned)sp[3] << 3);
                if (nib) atomicOr(&s_mask[tid >> 3], nib << (4 * (tid & 7)));
                __syncthreads();
                float rec[4] = {0.f, 0.f, 0.f, 0.f};
#pragma unroll 1
                for (int w = 0; w < 16; ++w) {
                    unsigned word = s_mask[w];
                    while (word) {
                        int j = (w << 5) + __ffs(word) - 1;
                        word &= word - 1;
                        float4 wv = *reinterpret_cast<const float4*>(
                            g_wrecT + j * NHID + 4 * tid);
                        rec[0] += wv.x; rec[1] += wv.y;
                        rec[2] += wv.z; rec[3] += wv.w;
                    }
                }
                __syncthreads();
#pragma unroll
                for (int i = 0; i < 4; ++i) psc[i] = psc[i] * D_SYN + rec[i];
            } else {
#pragma unroll
                for (int i = 0; i < 4; ++i) psc[i] *= D_SYN;
            }
        }
    }

    float4 r = make_float4(cnt[0] * (1.0f / T_STEPS), cnt[1] * (1.0f / T_STEPS),
                           cnt[2] * (1.0f / T_STEPS), cnt[3] * (1.0f / T_STEPS));
    reinterpret_cast<float4*>(g_rate)[b * (NHID / 4) + tid] = r;
}

// ---------------------------------------------------------------------------
// Output: out[b][o] = sum_h rate[b][h] * W_out[o][h]
// ---------------------------------------------------------------------------
__global__ void __launch_bounds__(128) out_kernel(const float* __restrict__ W_out,
                                                  float* __restrict__ out) {
    const int b = blockIdx.x;
    const int o = threadIdx.x;
    __shared__ float sr[NHID];
    for (int i = o; i < NHID; i += 128) sr[i] = g_rate[b * NHID + i];
    __syncthreads();

    float acc = 0.f;
    const float4* w = reinterpret_cast<const float4*>(W_out + o * NHID);
#pragma unroll 4
    for (int i = 0; i < NHID / 4; ++i) {
        float4 wv = w[i];
        acc += wv.x * sr[4 * i] + wv.y * sr[4 * i + 1]
             + wv.z * sr[4 * i + 2] + wv.w * sr[4 * i + 3];
    }
    out[b * NOUT + o] = acc;
}

// ---------------------------------------------------------------------------
// Launch
// ---------------------------------------------------------------------------
extern "C" void kernel_launch(void* const* d_in, const int* in_sizes, int n_in,
                              void* d_out, int out_size) {
    const float* x     = (const float*)d_in[0];   // (1000, 64, 256)
    const float* W_in  = (const float*)d_in[1];   // (512, 256)
    const float* W_rec = (const float*)d_in[2];   // (512, 512)
    const float* W_out = (const float*)d_in[3];   // (128, 512)
    float* out = (float*)d_out;                   // (64, 128)

    (void)in_sizes; (void)n_in; (void)out_size;

    cvt_w_kernel<<<128, 256>>>(reinterpret_cast<const float4*>(W_in));
    transpose_wrec_kernel<<<NHID, NHID>>>(W_rec);

    const int smem_bytes = 2 * BUFE * (int)sizeof(__nv_bfloat16);  // 61440
    cudaFuncSetAttribute(gemm_bf16_kernel,
                         cudaFuncAttributeMaxDynamicSharedMemorySize, smem_bytes);
    gemm_bf16_kernel<<<dim3(NHID / BNg, M_ROWS / BMg), 512, smem_bytes>>>(x);

    scanA_kernel<<<NCHUNK * BATCH, 128>>>();
    scanB_kernel<<<BATCH, 512>>>();
    scan_full_kernel<<<BATCH, 128>>>();

    out_kernel<<<BATCH, NOUT>>>(W_out, out);
}

// round 6
// speedup vs baseline: 6.1388x; 1.0834x over previous
#include <cuda_runtime.h>
#include <cuda_bf16.h>
#include <cstdint>

#define T_STEPS 1000
#define BATCH   64
#define NIN     256
#define NHID    512
#define NOUT    128
#define M_ROWS  (T_STEPS * BATCH)

#define V_TH     (-45.0f)
#define V_RESET  (-60.0f)
#define DT_CM    (0.5f)
#define D_ASC0   (0.9048374180359595f)
#define D_ASC1   (0.8187307530779818f)
#define D_SYN    (0.8187307530779818f)
#define AMP0     (1.0f)
#define AMP1     (-2.0f)
#define DECAY_V  (0.05f)

#define RINV10   (1.6701825701f)      // 0.95^-10
#define CHUNK    50
#define NCHUNK   20
#define A_CHUNK  (0.0769449727f)      // 0.95^50

__device__ __align__(128) __nv_bfloat16 g_xproj[(size_t)M_ROWS * NHID]; // [b][t][h]
__device__ __align__(128) __nv_bfloat16 g_wb[NHID * NIN];
__device__ __align__(128) float g_wrecT[NHID * NHID];
__device__ __align__(128) float g_rate[BATCH * NHID];
__device__ __align__(128) float g_chkB[NCHUNK * BATCH * NHID];
__device__ __align__(128) float g_chkT[NCHUNK * BATCH * NHID];
__device__ int g_bspike[BATCH];

static __device__ __forceinline__ uint32_t s2u(const void* p) {
    return (uint32_t)__cvta_generic_to_shared(p);
}
#define LDSM4(d0, d1, d2, d3, a)                                                 \
    asm volatile("ldmatrix.sync.aligned.m8n8.x4.shared.b16 {%0,%1,%2,%3}, [%4];" \
                 : "=r"(d0), "=r"(d1), "=r"(d2), "=r"(d3) : "r"(a))
#define MMA16816(ac, a0, a1, a2, a3, b0, b1)                                     \
    asm volatile("mma.sync.aligned.m16n8k16.row.col.f32.bf16.bf16.f32 "          \
                 "{%0,%1,%2,%3}, {%4,%5,%6,%7}, {%8,%9}, {%0,%1,%2,%3};\n"       \
                 : "+f"(ac[0]), "+f"(ac[1]), "+f"(ac[2]), "+f"(ac[3])            \
                 : "r"(a0), "r"(a1), "r"(a2), "r"(a3), "r"(b0), "r"(b1))

// Prep: blocks 0..511 transpose W_rec; blocks 512..639 convert W_in -> bf16.
__global__ void __launch_bounds__(256) prep_kernel(const float* __restrict__ W_in,
                                                   const float* __restrict__ W_rec) {
    const int bid = blockIdx.x, tid = threadIdx.x;
    if (bid < NHID) {
        g_wrecT[bid * NHID + tid]       = W_rec[tid * NHID + bid];
        g_wrecT[bid * NHID + tid + 256] = W_rec[(tid + 256) * NHID + bid];
    } else {
        int i = (bid - NHID) * 256 + tid;
        float4 v = reinterpret_cast<const float4*>(W_in)[i];
        reinterpret_cast<__nv_bfloat162*>(g_wb)[2 * i]     = __floats2bfloat162_rn(v.x, v.y);
        reinterpret_cast<__nv_bfloat162*>(g_wb)[2 * i + 1] = __floats2bfloat162_rn(v.z, v.w);
    }
}

// GEMM v5: 500 CTAs, 256 thr / 8 warps, BM=128 x full N=512 (4 slabs of 128).
// ldmatrix fragments; B double-buffered per k64 chunk; 2 CTAs/SM.
#define APITCH 264
#define BPITCH 72
#define SB_OFF (128 * APITCH)
#define SB_BUF (128 * BPITCH)
#define GEMM_SMEM ((SB_OFF + 2 * SB_BUF) * 2)   // 104448 B

__global__ void __launch_bounds__(256, 2) gemm_bf16_kernel(const float* __restrict__ x) {
    extern __shared__ __nv_bfloat16 smem[];
    __nv_bfloat16* sA = smem;               // [128][APITCH]
    __nv_bfloat16* sB = smem + SB_OFF;      // 2 x [128][BPITCH]

    const int tid  = threadIdx.x;
    const long tileM = (long)blockIdx.x * 128;
    const int warp = tid >> 5, lane = tid & 31;
    const int wm = warp & 1, wn = warp >> 1;
    const int g  = lane >> 2, tg = lane & 3;
    const int mat = lane >> 3, r8 = lane & 7;

    // stage A: 128x256 fp32 -> bf16
#pragma unroll 4
    for (int i = 0; i < 32; ++i) {
        int idx = tid + i * 256;
        int r = idx >> 6, c4 = idx & 63;
        float4 v = *reinterpret_cast<const float4*>(x + (tileM + r) * NIN + c4 * 4);
        __nv_bfloat162 lo = __floats2bfloat162_rn(v.x, v.y);
        __nv_bfloat162 hi = __floats2bfloat162_rn(v.z, v.w);
        uint2 pk = make_uint2(*reinterpret_cast<uint32_t*>(&lo),
                              *reinterpret_cast<uint32_t*>(&hi));
        *reinterpret_cast<uint2*>(sA + r * APITCH + c4 * 4) = pk;
    }
    // stage B (slab0, kc0) into buffer 0
#pragma unroll
    for (int i = 0; i < 4; ++i) {
        int idx = tid + i * 256;
        int r = idx >> 3, c8 = idx & 7;
        uint4 t = *reinterpret_cast<const uint4*>(g_wb + (long)r * NIN + c8 * 8);
        *reinterpret_cast<uint4*>(sB + r * BPITCH + c8 * 8) = t;
    }
    __syncthreads();

    const uint32_t sA32 = s2u(sA), sB32 = s2u(sB);
    uint32_t aBase[4];
#pragma unroll
    for (int mt = 0; mt < 4; ++mt)
        aBase[mt] = sA32 + (((wm * 64 + mt * 16 + (mat & 1) * 8 + r8) * APITCH)
                            + (mat >> 1) * 8) * 2;
    uint32_t bBase[2];
#pragma unroll
    for (int p2 = 0; p2 < 2; ++p2)
        bBase[p2] = (((wn * 32 + p2 * 16 + (mat >> 1) * 8 + r8) * BPITCH)
                     + (mat & 1) * 8) * 2;

    int p = 0;
#pragma unroll 1
    for (int slab = 0; slab < 4; ++slab) {
        float acc[4][4][4];
#pragma unroll
        for (int a = 0; a < 4; ++a)
#pragma unroll
            for (int b = 0; b < 4; ++b)
#pragma unroll
                for (int c = 0; c < 4; ++c) acc[a][b][c] = 0.f;

#pragma unroll 1
        for (int kc = 0; kc < 4; ++kc) {
            int nkc = kc + 1, nslab = slab;
            if (nkc == 4) { nkc = 0; ++nslab; }
            const bool valid = (nslab < 4);
            uint4 br[4];
            if (valid) {
#pragma unroll
                for (int i = 0; i < 4; ++i) {
                    int idx = tid + i * 256;
                    int r = idx >> 3, c8 = idx & 7;
                    br[i] = *reinterpret_cast<const uint4*>(
                        g_wb + (long)(nslab * 128 + r) * NIN + nkc * 64 + c8 * 8);
                }
            }

            const uint32_t bufo = sB32 + p * (SB_BUF * 2);
#pragma unroll
            for (int ks = 0; ks < 4; ++ks) {
                uint32_t af[4][4], bf[2][4];
#pragma unroll
                for (int mt = 0; mt < 4; ++mt)
                    LDSM4(af[mt][0], af[mt][1], af[mt][2], af[mt][3],
                          aBase[mt] + (kc * 64 + ks * 16) * 2);
#pragma unroll
                for (int p2 = 0; p2 < 2; ++p2)
                    LDSM4(bf[p2][0], bf[p2][1], bf[p2][2], bf[p2][3],
                          bufo + bBase[p2] + ks * 32);
#pragma unroll
                for (int mt = 0; mt < 4; ++mt)
#pragma unroll
                    for (int nt = 0; nt < 4; ++nt)
                        MMA16816(acc[mt][nt],
                                 af[mt][0], af[mt][1], af[mt][2], af[mt][3],
                                 bf[nt >> 1][(nt & 1) * 2],
                                 bf[nt >> 1][(nt & 1) * 2 + 1]);
            }

            if (valid) {
#pragma unroll
                for (int i = 0; i < 4; ++i) {
                    int idx = tid + i * 256;
                    int r = idx >> 3, c8 = idx & 7;
                    *reinterpret_cast<uint4*>(sB + (1 - p) * SB_BUF
                                              + r * BPITCH + c8 * 8) = br[i];
                }
            }
            __syncthreads();
            p ^= 1;
        }

        // epilogue: bf16 [b][t][h]
#pragma unroll
        for (int mt = 0; mt < 4; ++mt) {
            long m0 = tileM + wm * 64 + mt * 16 + g;
            long b0 = m0 & 63, t0 = m0 >> 6;
            long m1 = m0 + 8;
            long b1 = m1 & 63, t1 = m1 >> 6;
            __nv_bfloat16* d0 = g_xproj + (b0 * T_STEPS + t0) * NHID;
            __nv_bfloat16* d1 = g_xproj + (b1 * T_STEPS + t1) * NHID;
#pragma unroll
            for (int nt = 0; nt < 4; ++nt) {
                int col = slab * 128 + wn * 32 + nt * 8 + tg * 2;
                *reinterpret_cast<__nv_bfloat162*>(d0 + col) =
                    __floats2bfloat162_rn(acc[mt][nt][0], acc[mt][nt][1]);
                *reinterpret_cast<__nv_bfloat162*>(d1 + col) =
                    __floats2bfloat162_rn(acc[mt][nt][2], acc[mt][nt][3]);
            }
        }
    }
}

// scanA v2: 50-step chunks, E-transform.
// v(k)=0.95^k v0 + D_k; crossing iff v0 >= min_k (V_TH*invp_k - E_k),
// E_k = sum c_j*invp_j, c = 0.5*I - 3, invp_k = 0.95^-k. D_50 = E_50*0.95^50.
__global__ void __launch_bounds__(128) scanA_kernel() {
    const int tid = threadIdx.x;
    const int b = blockIdx.x & 63;
    const int c = blockIdx.x >> 6;          // 0..19
    const int t0g = c * CHUNK;

    const float CST[10] = {1.0526315789f, 1.1080332410f, 1.1663507800f,
                           1.2277376632f, 1.2923554349f, 1.3603741420f,
                           1.4319727810f, 1.5073397695f, 1.5866734416f,
                           1.6701825701f};

    const uint2* __restrict__ xp =
        reinterpret_cast<const uint2*>(g_xproj) + (long)b * (T_STEPS * NHID / 4) + tid;

    uint2 buf[10];
#pragma unroll
    for (int d = 0; d < 10; ++d) buf[d] = xp[(long)(t0g + d) * (NHID / 4)];

    float E[4]  = {0.f, 0.f, 0.f, 0.f};
    float th[4] = {1e30f, 1e30f, 1e30f, 1e30f};
    float invb  = 1.f;

#pragma unroll 1
    for (int tt = 0; tt < CHUNK; tt += 10) {
#pragma unroll
        for (int d = 0; d < 10; ++d) {
            uint2 raw = buf[d];
            int tp = t0g + tt + d + 10;
            if (tp > T_STEPS - 1) tp = T_STEPS - 1;
            buf[d] = xp[(long)tp * (NHID / 4)];

            float2 lo = __bfloat1622float2(*reinterpret_cast<__nv_bfloat162*>(&raw.x));
            float2 hi = __bfloat1622float2(*reinterpret_cast<__nv_bfloat162*>(&raw.y));
            float I[4] = {lo.x, lo.y, hi.x, hi.y};

            float ip  = invb * CST[d];
            float vth = V_TH * ip;
#pragma unroll
            for (int i = 0; i < 4; ++i) {
                float cc = fmaf(DT_CM, I[i], -3.0f);
                E[i] = fmaf(cc, ip, E[i]);
                th[i] = fminf(th[i], vth - E[i]);
            }
        }
        invb *= RINV10;
    }

    const long base = ((long)c * BATCH + b) * NHID + 4 * tid;
    *reinterpret_cast<float4*>(g_chkB + base) =
        make_float4(E[0] * A_CHUNK, E[1] * A_CHUNK, E[2] * A_CHUNK, E[3] * A_CHUNK);
    *reinterpret_cast<float4*>(g_chkT + base) = make_float4(th[0], th[1], th[2], th[3]);
}

// scanB: combine 20 chunk summaries; per-batch flag; zero rates.
__global__ void __launch_bounds__(512) scanB_kernel() {
    const int b = blockIdx.x;
    const int h = threadIdx.x;

    float v = V_RESET;
    int sp = 0;
#pragma unroll
    for (int c = 0; c < NCHUNK; ++c) {
        long idx = ((long)c * BATCH + b) * NHID + h;
        float th = g_chkT[idx];
        float Bd = g_chkB[idx];
        sp |= (v >= th);
        v = fmaf(A_CHUNK, v, Bd);
    }
    int any = __syncthreads_or(sp);
    if (h == 0) g_bspike[b] = any;
    g_rate[b * NHID + h] = 0.f;
}

// Fallback: full coupled simulation; runs only for batches that spiked.
#define PF2 8
__global__ void __launch_bounds__(128) scan_full_kernel() {
    const int b = blockIdx.x;
    if (g_bspike[b] == 0) return;

    const int tid = threadIdx.x;
    __shared__ unsigned s_mask[16];

    float v[4], a0[4], a1[4], psc[4], cnt[4];
#pragma unroll
    for (int i = 0; i < 4; ++i) {
        v[i] = V_RESET; a0[i] = 0.f; a1[i] = 0.f; psc[i] = 0.f; cnt[i] = 0.f;
    }

    const uint2* __restrict__ xp =
        reinterpret_cast<const uint2*>(g_xproj) + (long)b * (T_STEPS * NHID / 4) + tid;

    uint2 buf[PF2];
#pragma unroll
    for (int d = 0; d < PF2; ++d) buf[d] = xp[(long)d * (NHID / 4)];

    for (int t = 0; t < T_STEPS; t += PF2) {
#pragma unroll
        for (int d = 0; d < PF2; ++d) {
            uint2 raw = buf[d];
            int tn = t + d + PF2;
            if (tn > T_STEPS - 1) tn = T_STEPS - 1;
            buf[d] = xp[(long)tn * (NHID / 4)];

            float2 lo = __bfloat1622float2(*reinterpret_cast<__nv_bfloat162*>(&raw.x));
            float2 hi = __bfloat1622float2(*reinterpret_cast<__nv_bfloat162*>(&raw.y));
            float Ii[4] = {lo.x, lo.y, hi.x, hi.y};
            bool sp[4];
#pragma unroll
            for (int i = 0; i < 4; ++i) {
                float Itot  = Ii[i] + psc[i] + a0[i] + a1[i];
                float v_int = v[i] + DT_CM * Itot - DECAY_V * (v[i] - V_RESET);
                sp[i] = v_int >= V_TH;
                v[i]  = sp[i] ? V_RESET : v_int;
                a0[i] = a0[i] * D_ASC0 + (sp[i] ? AMP0 : 0.f);
                a1[i] = a1[i] * D_ASC1 + (sp[i] ? AMP1 : 0.f);
                cnt[i] += sp[i] ? 1.f : 0.f;
            }
            int anyl = (int)(sp[0] | sp[1] | sp[2] | sp[3]);

            if (__syncthreads_or(anyl)) {
                if (tid < 16) s_mask[tid] = 0;
                __syncthreads();
                unsigned nib = (unsigned)sp[0] | ((unsigned)sp[1] << 1)
                             | ((unsigned)sp[2] << 2) | ((unsigned)sp[3] << 3);
                if (nib) atomicOr(&s_mask[tid >> 3], nib << (4 * (tid & 7)));
                __syncthreads();
                float rec[4] = {0.f, 0.f, 0.f, 0.f};
#pragma unroll 1
                for (int w = 0; w < 16; ++w) {
                    unsigned word = s_mask[w];
                    while (word) {
                        int j = (w << 5) + __ffs(word) - 1;
                        word &= word - 1;
                        float4 wv = *reinterpret_cast<const float4*>(
                            g_wrecT + j * NHID + 4 * tid);
                        rec[0] += wv.x; rec[1] += wv.y;
                        rec[2] += wv.z; rec[3] += wv.w;
                    }
                }
                __syncthreads();
#pragma unroll
                for (int i = 0; i < 4; ++i) psc[i] = psc[i] * D_SYN + rec[i];
            } else {
#pragma unroll
                for (int i = 0; i < 4; ++i) psc[i] *= D_SYN;
            }
        }
    }

    float4 r = make_float4(cnt[0] * (1.0f / T_STEPS), cnt[1] * (1.0f / T_STEPS),
                           cnt[2] * (1.0f / T_STEPS), cnt[3] * (1.0f / T_STEPS));
    reinterpret_cast<float4*>(g_rate)[b * (NHID / 4) + tid] = r;
}

__global__ void __launch_bounds__(128) out_kernel(const float* __restrict__ W_out,
                                                  float* __restrict__ out) {
    const int b = blockIdx.x;
    const int o = threadIdx.x;
    __shared__ float sr[NHID];
    for (int i = o; i < NHID; i += 128) sr[i] = g_rate[b * NHID + i];
    __syncthreads();

    float acc = 0.f;
    const float4* w = reinterpret_cast<const float4*>(W_out + o * NHID);
#pragma unroll 4
    for (int i = 0; i < NHID / 4; ++i) {
        float4 wv = w[i];
        acc += wv.x * sr[4 * i] + wv.y * sr[4 * i + 1]
             + wv.z * sr[4 * i + 2] + wv.w * sr[4 * i + 3];
    }
    out[b * NOUT + o] = acc;
}

extern "C" void kernel_launch(void* const* d_in, const int* in_sizes, int n_in,
                              void* d_out, int out_size) {
    const float* x     = (const float*)d_in[0];
    const float* W_in  = (const float*)d_in[1];
    const float* W_rec = (const float*)d_in[2];
    const float* W_out = (const float*)d_in[3];
    float* out = (float*)d_out;
    (void)in_sizes; (void)n_in; (void)out_size;

    prep_kernel<<<NHID + 128, 256>>>(W_in, W_rec);

    cudaFuncSetAttribute(gemm_bf16_kernel,
                         cudaFuncAttributeMaxDynamicSharedMemorySize, GEMM_SMEM);
    gemm_bf16_kernel<<<M_ROWS / 128, 256, GEMM_SMEM>>>(x);

    scanA_kernel<<<NCHUNK * BATCH, 128>>>();
    scanB_kernel<<<BATCH, 512>>>();
    scan_full_kernel<<<BATCH, 128>>>();

    out_kernel<<<BATCH, NOUT>>>(W_out, out);
}